// round 12
// baseline (speedup 1.0000x reference)
#include <cuda_runtime.h>
#include <math.h>
#include <stdint.h>

#define SQ   1024
#define HID  768
#define NHD  12
#define DH   64
#define NG   4
#define NLAY 4
#define NEXP 8
#define FFD  3072
#define NVOC 50257
#define QKVN 1280   // 768 + 256 + 256

// ---------------- scratch (device globals; no allocation) ----------------
__device__ float g_h[SQ * HID];
__device__ float g_res[SQ * HID];
__device__ float g_qkv[SQ * QKVN];
__device__ float g_wqkv[NLAY * HID * QKVN];
__device__ float g_bqkv[NLAY * QKVN];
__device__ float g_h1[2 * SQ * FFD];
__device__ float g_eo[2 * SQ * HID];
__device__ float g_gates[SQ * 2];
__device__ int   g_texp[SQ * 2];
__device__ int   g_tlocal[SQ * 2];
__device__ int   g_tslot[SQ * 2];
__device__ int   g_cnt[NEXP];
__device__ int   g_offs[NEXP];
__device__ int   g_perm[2 * SQ];
__device__ int   g_loads[NLAY * NEXP];

// ---------------- embedding ----------------
__global__ void embed_kernel(const int* __restrict__ ids,
                             const float* __restrict__ emb,
                             const float* __restrict__ pos,
                             float* __restrict__ h) {
    int s = blockIdx.x;
    int id = ids[s];
    for (int c = threadIdx.x; c < HID; c += blockDim.x)
        h[(size_t)s * HID + c] = emb[(size_t)id * HID + c] + pos[(size_t)s * HID + c];
}

// ---------------- pack qw|kw|vw -> wqkv ----------------
__global__ __launch_bounds__(256) void pack_qkv_w(
    const float* __restrict__ qw, const float* __restrict__ kw,
    const float* __restrict__ vw, float* __restrict__ wqkv)
{
    size_t idx = (size_t)blockIdx.x * 256 + threadIdx.x;
    if (idx >= (size_t)NLAY * HID * QKVN) return;
    int j = (int)(idx % QKVN);
    size_t li = idx / QKVN;            // l*HID + i
    float v;
    if (j < HID)            v = qw[li * HID + j];
    else if (j < HID + 256) v = kw[li * 256 + (j - HID)];
    else                    v = vw[li * 256 + (j - HID - 256)];
    wqkv[idx] = v;
}

__global__ void pack_qkv_b(const float* __restrict__ qb, const float* __restrict__ kb,
                           const float* __restrict__ vb, float* __restrict__ bqkv)
{
    int idx = blockIdx.x * 256 + threadIdx.x;
    if (idx >= NLAY * QKVN) return;
    int l = idx / QKVN, j = idx % QKVN;
    float v;
    if (j < HID)            v = qb[l * HID + j];
    else if (j < HID + 256) v = kb[l * 256 + (j - HID)];
    else                    v = vb[l * 256 + (j - HID - 256)];
    bqkv[idx] = v;
}

// ---------------- tf32 helpers ----------------
__device__ __forceinline__ uint32_t f2tf(float x) {
    uint32_t r;
    asm("cvt.rna.tf32.f32 %0, %1;" : "=r"(r) : "f"(x));
    return r;
}

__device__ __forceinline__ void mma_tf32(float c[4],
                                         uint32_t a0, uint32_t a1, uint32_t a2, uint32_t a3,
                                         uint32_t b0, uint32_t b1) {
    asm volatile(
        "mma.sync.aligned.m16n8k8.row.col.f32.tf32.tf32.f32 "
        "{%0,%1,%2,%3}, {%4,%5,%6,%7}, {%8,%9}, {%0,%1,%2,%3};"
        : "+f"(c[0]), "+f"(c[1]), "+f"(c[2]), "+f"(c[3])
        : "r"(a0), "r"(a1), "r"(a2), "r"(a3), "r"(b0), "r"(b1));
}

__device__ __forceinline__ uint4 tf_pack(float v0, float v4) {
    uint4 p;
    p.x = f2tf(v0);
    p.y = f2tf(v4);
    p.z = f2tf(v0 - __uint_as_float(p.x));
    p.w = f2tf(v4 - __uint_as_float(p.y));
    return p;
}

// ---------------- bf16 helpers ----------------
__device__ __forceinline__ uint32_t bf16pack2(float x0, float x1) {
    uint32_t r;
    asm("cvt.rn.bf16x2.f32 %0, %1, %2;" : "=r"(r) : "f"(x1), "f"(x0));
    return r;
}
__device__ __forceinline__ void bf16split2(float x0, float x1, uint32_t& hi, uint32_t& lo) {
    hi = bf16pack2(x0, x1);
    float h0 = __uint_as_float(hi << 16);
    float h1 = __uint_as_float(hi & 0xFFFF0000u);
    lo = bf16pack2(x0 - h0, x1 - h1);
}

__device__ __forceinline__ void mma_bf16(float c[4],
                                         uint32_t a0, uint32_t a1, uint32_t a2, uint32_t a3,
                                         uint32_t b0, uint32_t b1) {
    asm volatile(
        "mma.sync.aligned.m16n8k16.row.col.f32.bf16.bf16.f32 "
        "{%0,%1,%2,%3}, {%4,%5,%6,%7}, {%8,%9}, {%0,%1,%2,%3};"
        : "+f"(c[0]), "+f"(c[1]), "+f"(c[2]), "+f"(c[3])
        : "r"(a0), "r"(a1), "r"(a2), "r"(a3), "r"(b0), "r"(b1));
}

#define ASTG 576            // 64 rows * 9 uint4
#define GEMM_SMEM_MAX (2 * (ASTG + 128 * 9) * 16)   // NTILE=128 case (55296)

// ---------------- 3xTF32 GEMM: 64(M)xNTILE(N) tile, double-buffered ----
template<bool GELU, bool EXPERT, bool GATHER, int NTILE>
__global__ __launch_bounds__(256, 2) void mma_gemm(
    const float* __restrict__ A, const float* __restrict__ B,
    const float* __restrict__ bias, float* __restrict__ C,
    int M, int N, int K, int lda, int ldc,
    const int* __restrict__ perm, const int* __restrict__ offs,
    const int* __restrict__ cnts, size_t strideB, size_t strideBias)
{
    constexpr int NFN   = NTILE / 32;   // fn count per warp; also B j count
    constexpr int BGRP  = 256 / NTILE;  // kq group stride
    constexpr int BSTGv = NTILE * 9;

    extern __shared__ uint4 sm4[];
    uint4* AP = sm4;                 // [2][ASTG]
    uint4* BP = sm4 + 2 * ASTG;      // [2][BSTGv]

    int mcount = M, base = 0;
    if (EXPERT) {
        int e = blockIdx.z;
        mcount = cnts[e];
        base   = offs[e];
        B     += (size_t)e * strideB;
        bias  += (size_t)e * strideBias;
    }
    int m0 = blockIdx.y * 64;
    if (m0 >= mcount) return;
    int n0 = blockIdx.x * NTILE;

    int tid = threadIdx.x, lane = tid & 31, warp = tid >> 5;
    int wm = (warp & 1) * 32;
    int wn = (warp >> 1) * (NTILE / 4);

    int aRow = tid >> 1;
    int aKK  = tid & 1;
    bool aprod = (tid < 128);
    bool aok = aprod && (m0 + aRow < mcount);
    const float* aptr = A;
    if (aok) {
        int phys = GATHER ? perm[base + m0 + aRow]
                          : (EXPERT ? base + m0 + aRow : m0 + aRow);
        aptr = A + (size_t)phys * (size_t)lda;
    }
    int bN   = tid & (NTILE - 1);
    int bKQ0 = tid / NTILE;
    int gn   = n0 + bN;
    bool bok = (gn < N);

    float c[2][NFN][4];
#pragma unroll
    for (int i = 0; i < 2; i++)
#pragma unroll
        for (int j = 0; j < NFN; j++)
#pragma unroll
            for (int q = 0; q < 4; q++) c[i][j][q] = 0.f;

    float stA[8], stB[NFN * 2];

    if (aprod) {
        float4 v0 = make_float4(0.f,0.f,0.f,0.f), v1 = v0;
        if (aok) {
            v0 = *(const float4*)(aptr + aKK * 8);
            v1 = *(const float4*)(aptr + aKK * 8 + 4);
        }
        stA[0]=v0.x; stA[1]=v0.y; stA[2]=v0.z; stA[3]=v0.w;
        stA[4]=v1.x; stA[5]=v1.y; stA[6]=v1.z; stA[7]=v1.w;
    }
#pragma unroll
    for (int j = 0; j < NFN; j++) {
        int kq = bKQ0 + BGRP * j;
        int krow = (kq >> 2) * 8 + (kq & 3);
        float b0 = 0.f, b1 = 0.f;
        if (bok) {
            b0 = B[(size_t)krow * (size_t)N + gn];
            b1 = B[(size_t)(krow + 4) * (size_t)N + gn];
        }
        stB[j * 2] = b0; stB[j * 2 + 1] = b1;
    }
    if (aprod) {
#pragma unroll
        for (int q = 0; q < 4; q++)
            AP[aRow * 9 + aKK * 4 + q] = tf_pack(stA[q], stA[q + 4]);
    }
#pragma unroll
    for (int j = 0; j < NFN; j++) {
        int kq = bKQ0 + BGRP * j;
        BP[bN * 9 + kq] = tf_pack(stB[j * 2], stB[j * 2 + 1]);
    }
    __syncthreads();

    int buf = 0;
    for (int k0 = 0; k0 < K; k0 += 16) {
        bool has_next = (k0 + 16 < K);
        if (has_next) {
            if (aprod) {
                float4 v0 = make_float4(0.f,0.f,0.f,0.f), v1 = v0;
                if (aok) {
                    v0 = *(const float4*)(aptr + k0 + 16 + aKK * 8);
                    v1 = *(const float4*)(aptr + k0 + 16 + aKK * 8 + 4);
                }
                stA[0]=v0.x; stA[1]=v0.y; stA[2]=v0.z; stA[3]=v0.w;
                stA[4]=v1.x; stA[5]=v1.y; stA[6]=v1.z; stA[7]=v1.w;
            }
#pragma unroll
            for (int j = 0; j < NFN; j++) {
                int kq = bKQ0 + BGRP * j;
                int krow = k0 + 16 + (kq >> 2) * 8 + (kq & 3);
                float b0 = 0.f, b1 = 0.f;
                if (bok) {
                    b0 = B[(size_t)krow * (size_t)N + gn];
                    b1 = B[(size_t)(krow + 4) * (size_t)N + gn];
                }
                stB[j * 2] = b0; stB[j * 2 + 1] = b1;
            }
        }

        const uint4* APc = AP + buf * ASTG;
        const uint4* BPc = BP + buf * BSTGv;
        int ra = lane >> 2;
        int q  = lane & 3;
#pragma unroll
        for (int kk = 0; kk < 2; kk++) {
            int kkq = kk * 4 + q;
            uint32_t aH[2][4], aL[2][4];
#pragma unroll
            for (int fm = 0; fm < 2; fm++) {
                int m = wm + fm * 16 + ra;
                uint4 f0 = APc[m * 9 + kkq];
                uint4 f1 = APc[(m + 8) * 9 + kkq];
                aH[fm][0] = f0.x; aH[fm][1] = f1.x;
                aH[fm][2] = f0.y; aH[fm][3] = f1.y;
                aL[fm][0] = f0.z; aL[fm][1] = f1.z;
                aL[fm][2] = f0.w; aL[fm][3] = f1.w;
            }
#pragma unroll
            for (int fn = 0; fn < NFN; fn++) {
                int n = wn + fn * 8 + ra;
                uint4 fb = BPc[n * 9 + kkq];
#pragma unroll
                for (int fm = 0; fm < 2; fm++) {
                    mma_tf32(c[fm][fn], aL[fm][0], aL[fm][1], aL[fm][2], aL[fm][3], fb.x, fb.y);
                    mma_tf32(c[fm][fn], aH[fm][0], aH[fm][1], aH[fm][2], aH[fm][3], fb.z, fb.w);
                    mma_tf32(c[fm][fn], aH[fm][0], aH[fm][1], aH[fm][2], aH[fm][3], fb.x, fb.y);
                }
            }
        }

        if (has_next) {
            uint4* APn = AP + (buf ^ 1) * ASTG;
            uint4* BPn = BP + (buf ^ 1) * BSTGv;
            if (aprod) {
#pragma unroll
                for (int qq = 0; qq < 4; qq++)
                    APn[aRow * 9 + aKK * 4 + qq] = tf_pack(stA[qq], stA[qq + 4]);
            }
#pragma unroll
            for (int j = 0; j < NFN; j++) {
                int kq = bKQ0 + BGRP * j;
                BPn[bN * 9 + kq] = tf_pack(stB[j * 2], stB[j * 2 + 1]);
            }
        }
        __syncthreads();
        buf ^= 1;
    }

#pragma unroll
    for (int fm = 0; fm < 2; fm++) {
#pragma unroll
        for (int half = 0; half < 2; half++) {
            int mrel = m0 + wm + fm * 16 + (lane >> 2) + half * 8;
            if (mrel >= mcount) continue;
            size_t crow = (size_t)(EXPERT ? base + mrel : mrel) * (size_t)ldc;
#pragma unroll
            for (int fn = 0; fn < NFN; fn++) {
                int n = n0 + wn + fn * 8 + (lane & 3) * 2;
                float v0 = c[fm][fn][half * 2 + 0];
                float v1 = c[fm][fn][half * 2 + 1];
                if (n < N) {
                    float o = v0 + bias[n];
                    if (GELU) o = 0.5f * o * (1.f + erff(o * 0.70710678118654752f));
                    C[crow + n] = o;
                }
                if (n + 1 < N) {
                    float o = v1 + bias[n + 1];
                    if (GELU) o = 0.5f * o * (1.f + erff(o * 0.70710678118654752f));
                    C[crow + n + 1] = o;
                }
            }
        }
    }
}

// ---------------- 2xBF16 GEMM for the final logits projection --------------
// grid: (M-tiles, N-tiles) — M fastest so consecutive CTAs share the B slice (L2 reuse)
#define BA_STG (64 * 5)
#define BB_STG (128 * 5)
#define GEMM_SMEM_BF (2 * (BA_STG + BB_STG) * 16)   // 30720 bytes

__global__ __launch_bounds__(256, 2) void mma_gemm_bf16(
    const float* __restrict__ A, const float* __restrict__ B,
    const float* __restrict__ bias, float* __restrict__ C,
    int M, int N, int K, int lda, int ldc)
{
    extern __shared__ uint4 sm4[];
    uint4* AP = sm4;
    uint4* BP = sm4 + 2 * BA_STG;

    int m0 = blockIdx.x * 64;      // M fastest-varying
    int n0 = blockIdx.y * 128;

    int tid = threadIdx.x, lane = tid & 31, warp = tid >> 5;
    int wm = (warp & 1) * 32;
    int wn = (warp >> 1) * 32;

    int aRow = tid >> 1;
    int aH2  = tid & 1;
    bool aprod = (tid < 128);
    bool aok = aprod && (m0 + aRow < M);
    const float* aptr = A + (size_t)(m0 + aRow) * (size_t)lda;

    int bN = tid & 127;
    int bH = tid >> 7;
    int gn = n0 + bN;
    bool bok = (gn < N);

    float c[2][4][4];
#pragma unroll
    for (int i = 0; i < 2; i++)
#pragma unroll
        for (int j = 0; j < 4; j++)
#pragma unroll
            for (int q = 0; q < 4; q++) c[i][j][q] = 0.f;

    float sA[8], sB[8];

    if (aprod) {
        float4 v0 = make_float4(0.f,0.f,0.f,0.f), v1 = v0;
        if (aok) {
            v0 = *(const float4*)(aptr + aH2 * 4);
            v1 = *(const float4*)(aptr + aH2 * 4 + 8);
        }
        sA[0]=v0.x; sA[1]=v0.y; sA[2]=v0.z; sA[3]=v0.w;
        sA[4]=v1.x; sA[5]=v1.y; sA[6]=v1.z; sA[7]=v1.w;
    }
#pragma unroll
    for (int j = 0; j < 2; j++) {
        int q = 2 * bH + j;
        int k = 2 * q;
        float b0 = 0.f, b1 = 0.f, b2 = 0.f, b3 = 0.f;
        if (bok) {
            b0 = B[(size_t)k * N + gn];
            b1 = B[(size_t)(k + 1) * N + gn];
            b2 = B[(size_t)(k + 8) * N + gn];
            b3 = B[(size_t)(k + 9) * N + gn];
        }
        sB[j*4+0]=b0; sB[j*4+1]=b1; sB[j*4+2]=b2; sB[j*4+3]=b3;
    }
    if (aprod) {
#pragma unroll
        for (int j = 0; j < 2; j++) {
            uint4 p;
            bf16split2(sA[j*2+0], sA[j*2+1], p.x, p.z);
            bf16split2(sA[j*2+4], sA[j*2+5], p.y, p.w);
            AP[aRow * 5 + 2 * aH2 + j] = p;
        }
    }
#pragma unroll
    for (int j = 0; j < 2; j++) {
        uint4 p;
        bf16split2(sB[j*4+0], sB[j*4+1], p.x, p.z);
        bf16split2(sB[j*4+2], sB[j*4+3], p.y, p.w);
        BP[bN * 5 + 2 * bH + j] = p;
    }
    __syncthreads();

    int buf = 0;
    for (int k0 = 0; k0 < K; k0 += 16) {
        bool has_next = (k0 + 16 < K);
        if (has_next) {
            if (aprod) {
                float4 v0 = make_float4(0.f,0.f,0.f,0.f), v1 = v0;
                if (aok) {
                    v0 = *(const float4*)(aptr + k0 + 16 + aH2 * 4);
                    v1 = *(const float4*)(aptr + k0 + 16 + aH2 * 4 + 8);
                }
                sA[0]=v0.x; sA[1]=v0.y; sA[2]=v0.z; sA[3]=v0.w;
                sA[4]=v1.x; sA[5]=v1.y; sA[6]=v1.z; sA[7]=v1.w;
            }
#pragma unroll
            for (int j = 0; j < 2; j++) {
                int q = 2 * bH + j;
                int k = k0 + 16 + 2 * q;
                float b0 = 0.f, b1 = 0.f, b2 = 0.f, b3 = 0.f;
                if (bok) {
                    b0 = B[(size_t)k * N + gn];
                    b1 = B[(size_t)(k + 1) * N + gn];
                    b2 = B[(size_t)(k + 8) * N + gn];
                    b3 = B[(size_t)(k + 9) * N + gn];
                }
                sB[j*4+0]=b0; sB[j*4+1]=b1; sB[j*4+2]=b2; sB[j*4+3]=b3;
            }
        }

        const uint4* APc = AP + buf * BA_STG;
        const uint4* BPc = BP + buf * BB_STG;
        int ra = lane >> 2;
        int q  = lane & 3;
        uint32_t aHf[2][4], aLf[2][4];
#pragma unroll
        for (int fm = 0; fm < 2; fm++) {
            int m = wm + fm * 16 + ra;
            uint4 f0 = APc[m * 5 + q];
            uint4 f1 = APc[(m + 8) * 5 + q];
            aHf[fm][0] = f0.x; aHf[fm][1] = f1.x;
            aHf[fm][2] = f0.y; aHf[fm][3] = f1.y;
            aLf[fm][0] = f0.z; aLf[fm][1] = f1.z;
            aLf[fm][2] = f0.w; aLf[fm][3] = f1.w;
        }
#pragma unroll
        for (int fn = 0; fn < 4; fn++) {
            int n = wn + fn * 8 + ra;
            uint4 fb = BPc[n * 5 + q];
#pragma unroll
            for (int fm = 0; fm < 2; fm++) {
                mma_bf16(c[fm][fn], aLf[fm][0], aLf[fm][1], aLf[fm][2], aLf[fm][3], fb.x, fb.y);
                mma_bf16(c[fm][fn], aHf[fm][0], aHf[fm][1], aHf[fm][2], aHf[fm][3], fb.z, fb.w);
                mma_bf16(c[fm][fn], aHf[fm][0], aHf[fm][1], aHf[fm][2], aHf[fm][3], fb.x, fb.y);
            }
        }

        if (has_next) {
            uint4* APn = AP + (buf ^ 1) * BA_STG;
            uint4* BPn = BP + (buf ^ 1) * BB_STG;
            if (aprod) {
#pragma unroll
                for (int j = 0; j < 2; j++) {
                    uint4 p;
                    bf16split2(sA[j*2+0], sA[j*2+1], p.x, p.z);
                    bf16split2(sA[j*2+4], sA[j*2+5], p.y, p.w);
                    APn[aRow * 5 + 2 * aH2 + j] = p;
                }
            }
#pragma unroll
            for (int j = 0; j < 2; j++) {
                uint4 p;
                bf16split2(sB[j*4+0], sB[j*4+1], p.x, p.z);
                bf16split2(sB[j*4+2], sB[j*4+3], p.y, p.w);
                BPn[bN * 5 + 2 * bH + j] = p;
            }
        }
        __syncthreads();
        buf ^= 1;
    }

#pragma unroll
    for (int fm = 0; fm < 2; fm++) {
#pragma unroll
        for (int half = 0; half < 2; half++) {
            int mrel = m0 + wm + fm * 16 + (lane >> 2) + half * 8;
            if (mrel >= M) continue;
            size_t crow = (size_t)mrel * (size_t)ldc;
#pragma unroll
            for (int fn = 0; fn < 4; fn++) {
                int n = n0 + wn + fn * 8 + (lane & 3) * 2;
                if (n < N)     C[crow + n]     = c[fm][fn][half * 2 + 0] + bias[n];
                if (n + 1 < N) C[crow + n + 1] = c[fm][fn][half * 2 + 1] + bias[n + 1];
            }
        }
    }
}

// ---------------- flash-style GQA attention (fp32, reads combined QKV) ----------------
__global__ __launch_bounds__(256) void attn_kernel(
    const float* __restrict__ qkv, const int* __restrict__ amask,
    float* __restrict__ ao)
{
    const float SCALE = 0.125f;
    int head = blockIdx.y;
    int g    = head / (NHD / NG);
    int q0   = blockIdx.x * 64;

    __shared__ float QsT[64][68];
    __shared__ float KsT[64][33];
    __shared__ float Vs [32][68];
    __shared__ float PsT[32][68];
    __shared__ float Mk [32];

    int tid = threadIdx.x;
#pragma unroll
    for (int i = 0; i < 4; i++) {
        int idx = tid + i * 256;
        int r = idx >> 4;
        int dseg = (idx & 15) * 4;
        float4 qv = *(const float4*)(qkv + (size_t)(q0 + r) * QKVN + head * 64 + dseg);
        QsT[dseg + 0][r] = qv.x; QsT[dseg + 1][r] = qv.y;
        QsT[dseg + 2][r] = qv.z; QsT[dseg + 3][r] = qv.w;
    }

    int rg = tid >> 4, kg = tid & 15;
    int r0 = rg * 4, d0 = kg * 4, j0 = kg * 2;

    float acc[4][4] = {};
    float m[4], l[4];
#pragma unroll
    for (int i = 0; i < 4; i++) { m[i] = -3.0e38f; l[i] = 0.f; }

    for (int kc = 0; kc < 32; kc++) {
        int kbase = kc * 32;
#pragma unroll
        for (int i = 0; i < 2; i++) {
            int idx = tid + i * 256;
            int kk = idx >> 4;
            int dseg = (idx & 15) * 4;
            float4 kv = *(const float4*)(qkv + (size_t)(kbase + kk) * QKVN + HID + g * 64 + dseg);
            KsT[dseg + 0][kk] = kv.x; KsT[dseg + 1][kk] = kv.y;
            KsT[dseg + 2][kk] = kv.z; KsT[dseg + 3][kk] = kv.w;
            float4 vv = *(const float4*)(qkv + (size_t)(kbase + kk) * QKVN + HID + 256 + g * 64 + dseg);
            *(float4*)&Vs[kk][dseg] = vv;
        }
        if (tid < 32) Mk[tid] = (amask[kbase + tid] == 0) ? -3.0e38f : 0.f;
        __syncthreads();

        float s0[4] = {}, s1[4] = {};
#pragma unroll
        for (int d = 0; d < 64; d++) {
            float4 a = *(const float4*)&QsT[d][r0];
            float b0 = KsT[d][j0], b1 = KsT[d][j0 + 1];
            s0[0] += a.x * b0; s1[0] += a.x * b1;
            s0[1] += a.y * b0; s1[1] += a.y * b1;
            s0[2] += a.z * b0; s1[2] += a.z * b1;
            s0[3] += a.w * b0; s1[3] += a.w * b1;
        }
        float mk0 = Mk[j0], mk1 = Mk[j0 + 1];
        float cm[4];
#pragma unroll
        for (int i = 0; i < 4; i++) {
            s0[i] = s0[i] * SCALE + mk0;
            s1[i] = s1[i] * SCALE + mk1;
            cm[i] = fmaxf(s0[i], s1[i]);
        }
#pragma unroll
        for (int o = 1; o < 16; o <<= 1)
#pragma unroll
            for (int i = 0; i < 4; i++)
                cm[i] = fmaxf(cm[i], __shfl_xor_sync(0xffffffffu, cm[i], o));

        float p0[4], p1[4], csum[4];
#pragma unroll
        for (int i = 0; i < 4; i++) {
            float nm = fmaxf(m[i], cm[i]);
            float alpha = expf(m[i] - nm);
            m[i] = nm;
            p0[i] = expf(s0[i] - nm);
            p1[i] = expf(s1[i] - nm);
            csum[i] = p0[i] + p1[i];
            l[i] *= alpha;
#pragma unroll
            for (int j = 0; j < 4; j++) acc[i][j] *= alpha;
        }
#pragma unroll
        for (int o = 1; o < 16; o <<= 1)
#pragma unroll
            for (int i = 0; i < 4; i++)
                csum[i] += __shfl_xor_sync(0xffffffffu, csum[i], o);
#pragma unroll
        for (int i = 0; i < 4; i++) l[i] += csum[i];

#pragma unroll
        for (int i = 0; i < 4; i++) {
            PsT[j0][r0 + i]     = p0[i];
            PsT[j0 + 1][r0 + i] = p1[i];
        }
        __syncthreads();

#pragma unroll
        for (int key = 0; key < 32; key++) {
            float4 pv = *(const float4*)&PsT[key][r0];
            float4 vv = *(const float4*)&Vs[key][d0];
            acc[0][0] += pv.x * vv.x; acc[0][1] += pv.x * vv.y; acc[0][2] += pv.x * vv.z; acc[0][3] += pv.x * vv.w;
            acc[1][0] += pv.y * vv.x; acc[1][1] += pv.y * vv.y; acc[1][2] += pv.y * vv.z; acc[1][3] += pv.y * vv.w;
            acc[2][0] += pv.z * vv.x; acc[2][1] += pv.z * vv.y; acc[2][2] += pv.z * vv.z; acc[2][3] += pv.z * vv.w;
            acc[3][0] += pv.w * vv.x; acc[3][1] += pv.w * vv.y; acc[3][2] += pv.w * vv.z; acc[3][3] += pv.w * vv.w;
        }
        __syncthreads();
    }

#pragma unroll
    for (int i = 0; i < 4; i++) {
        float inv = 1.f / l[i];
        float4 o;
        o.x = acc[i][0] * inv; o.y = acc[i][1] * inv;
        o.z = acc[i][2] * inv; o.w = acc[i][3] * inv;
        *(float4*)(ao + (size_t)(q0 + r0 + i) * HID + head * 64 + d0) = o;
    }
}

// ---------------- layernorm: h = LN(h + res) ----------------
__global__ __launch_bounds__(256) void ln_kernel(float* __restrict__ h,
                                                 const float* __restrict__ res,
                                                 const float* __restrict__ gam,
                                                 const float* __restrict__ bet) {
    int row = blockIdx.x;
    __shared__ float xbuf[HID];
    __shared__ float red[256];
    int tid = threadIdx.x;
    float lsum = 0.f;
    for (int c = tid; c < HID; c += 256) {
        float v = h[(size_t)row * HID + c] + res[(size_t)row * HID + c];
        xbuf[c] = v;
        lsum += v;
    }
    red[tid] = lsum; __syncthreads();
    for (int s = 128; s > 0; s >>= 1) { if (tid < s) red[tid] += red[tid + s]; __syncthreads(); }
    float mean = red[0] / (float)HID;
    __syncthreads();
    float lvar = 0.f;
    for (int c = tid; c < HID; c += 256) { float d = xbuf[c] - mean; lvar += d * d; }
    red[tid] = lvar; __syncthreads();
    for (int s = 128; s > 0; s >>= 1) { if (tid < s) red[tid] += red[tid + s]; __syncthreads(); }
    float rstd = rsqrtf(red[0] / (float)HID + 1e-5f);
    for (int c = tid; c < HID; c += 256)
        h[(size_t)row * HID + c] = (xbuf[c] - mean) * rstd * gam[c] + bet[c];
}

// ---------------- router: top-2 gating ----------------
__global__ __launch_bounds__(256) void router_kernel(
    const float* __restrict__ h, const float* __restrict__ rw,
    const float* __restrict__ rb, float* __restrict__ gates,
    int* __restrict__ texp, int* __restrict__ tlocal, int* __restrict__ cnt)
{
    int t = blockIdx.x;
    int tid = threadIdx.x;
    int e = tid >> 5, lane = tid & 31;
    float sum = 0.f;
    for (int i = lane; i < HID; i += 32)
        sum += h[(size_t)t * HID + i] * rw[i * NEXP + e];
#pragma unroll
    for (int o = 16; o > 0; o >>= 1) sum += __shfl_down_sync(0xffffffffu, sum, o);
    __shared__ float logits[NEXP];
    if (lane == 0) logits[e] = sum + rb[e];
    __syncthreads();
    if (tid == 0) {
        float mx = logits[0];
        for (int i = 1; i < NEXP; i++) mx = fmaxf(mx, logits[i]);
        float ex[NEXP], ssum = 0.f;
        for (int i = 0; i < NEXP; i++) { ex[i] = expf(logits[i] - mx); ssum += ex[i]; }
        float p[NEXP];
        for (int i = 0; i < NEXP; i++) p[i] = ex[i] / ssum;
        int i0 = 0;
        for (int i = 1; i < NEXP; i++) if (p[i] > p[i0]) i0 = i;
        int i1 = (i0 == 0) ? 1 : 0;
        for (int i = 0; i < NEXP; i++) if (i != i0 && p[i] > p[i1]) i1 = i;
        float b = expf(p[i1] - p[i0]);
        float g0 = 1.f / (1.f + b);
        float g1 = b / (1.f + b);
        gates[t * 2] = g0; gates[t * 2 + 1] = g1;
        texp[t * 2] = i0; texp[t * 2 + 1] = i1;
        tlocal[t * 2]     = atomicAdd(&cnt[i0], 1);
        tlocal[t * 2 + 1] = atomicAdd(&cnt[i1], 1);
    }
}

__global__ void zero_cnt_kernel(int* c) { if (threadIdx.x < NEXP) c[threadIdx.x] = 0; }

__global__ __launch_bounds__(256) void assign_kernel(
    const int* __restrict__ cnt, int* __restrict__ offs, int* __restrict__ perm,
    const int* __restrict__ texp, const int* __restrict__ tlocal,
    int* __restrict__ tslot, int* __restrict__ loads)
{
    __shared__ int so[NEXP];
    if (threadIdx.x == 0) {
        int acc = 0;
        for (int e = 0; e < NEXP; e++) {
            so[e] = acc; offs[e] = acc; loads[e] = cnt[e]; acc += cnt[e];
        }
    }
    __syncthreads();
    for (int i = threadIdx.x; i < 2 * SQ; i += blockDim.x) {
        int t = i >> 1;
        int slot = so[texp[i]] + tlocal[i];
        perm[slot] = t;
        tslot[i] = slot;
    }
}

__global__ __launch_bounds__(256) void combine_kernel(
    const float* __restrict__ eo, const float* __restrict__ gates,
    const int* __restrict__ tslot, float* __restrict__ res)
{
    int t = blockIdx.x;
    int s0 = tslot[t * 2], s1 = tslot[t * 2 + 1];
    float g0 = gates[t * 2], g1 = gates[t * 2 + 1];
    for (int c = threadIdx.x; c < HID; c += 256)
        res[(size_t)t * HID + c] = g0 * eo[(size_t)s0 * HID + c] + g1 * eo[(size_t)s1 * HID + c];
}

__global__ void loss_kernel(const int* __restrict__ loads, float* __restrict__ out) {
    int l = threadIdx.x;
    if (l < NLAY) {
        float mean = (float)(2 * SQ) / (float)NEXP;
        float var = 0.f;
        for (int e = 0; e < NEXP; e++) {
            float d = (float)loads[l * NEXP + e] - mean;
            var += d * d;
        }
        var /= (float)(NEXP - 1);
        out[l] = var / (mean * mean);
    }
}

// ---------------- host launch ----------------
#define SMEM_N64  (2 * (ASTG + 64 * 9) * 16)
#define SMEM_N128 (2 * (ASTG + 128 * 9) * 16)

extern "C" void kernel_launch(void* const* d_in, const int* in_sizes, int n_in,
                              void* d_out, int out_size) {
    const int*   ids   = (const int*)d_in[0];
    const int*   amask = (const int*)d_in[1];
    const float* emb   = (const float*)d_in[2];
    const float* pos   = (const float*)d_in[3];
    const float* qw    = (const float*)d_in[4];
    const float* qb    = (const float*)d_in[5];
    const float* kw    = (const float*)d_in[6];
    const float* kb    = (const float*)d_in[7];
    const float* vw    = (const float*)d_in[8];
    const float* vb    = (const float*)d_in[9];
    const float* rw    = (const float*)d_in[10];
    const float* rb    = (const float*)d_in[11];
    const float* fc1w  = (const float*)d_in[12];
    const float* fc1b  = (const float*)d_in[13];
    const float* fc2w  = (const float*)d_in[14];
    const float* fc2b  = (const float*)d_in[15];
    const float* lng   = (const float*)d_in[16];
    const float* lnb   = (const float*)d_in[17];
    const float* ow    = (const float*)d_in[18];
    const float* ob    = (const float*)d_in[19];
    float* out = (float*)d_out;

    cudaFuncSetAttribute(mma_gemm<false, false, false, 64>,
                         cudaFuncAttributeMaxDynamicSharedMemorySize, SMEM_N64);
    cudaFuncSetAttribute(mma_gemm<true, true, true, 128>,
                         cudaFuncAttributeMaxDynamicSharedMemorySize, SMEM_N128);
    cudaFuncSetAttribute(mma_gemm<false, true, false, 64>,
                         cudaFuncAttributeMaxDynamicSharedMemorySize, SMEM_N64);
    cudaFuncSetAttribute(mma_gemm_bf16,
                         cudaFuncAttributeMaxDynamicSharedMemorySize, GEMM_SMEM_BF);

    float *h, *res, *qkv, *wqkv, *bqkv, *h1, *eo, *gates;
    int *texp, *tlocal, *tslot, *cnt, *offs, *perm, *loads;
    cudaGetSymbolAddress((void**)&h, g_h);
    cudaGetSymbolAddress((void**)&res, g_res);
    cudaGetSymbolAddress((void**)&qkv, g_qkv);
    cudaGetSymbolAddress((void**)&wqkv, g_wqkv);
    cudaGetSymbolAddress((void**)&bqkv, g_bqkv);
    cudaGetSymbolAddress((void**)&h1, g_h1);
    cudaGetSymbolAddress((void**)&eo, g_eo);
    cudaGetSymbolAddress((void**)&gates, g_gates);
    cudaGetSymbolAddress((void**)&texp, g_texp);
    cudaGetSymbolAddress((void**)&tlocal, g_tlocal);
    cudaGetSymbolAddress((void**)&tslot, g_tslot);
    cudaGetSymbolAddress((void**)&cnt, g_cnt);
    cudaGetSymbolAddress((void**)&offs, g_offs);
    cudaGetSymbolAddress((void**)&perm, g_perm);
    cudaGetSymbolAddress((void**)&loads, g_loads);

    {
        size_t tot = (size_t)NLAY * HID * QKVN;
        pack_qkv_w<<<(unsigned)((tot + 255) / 256), 256>>>(qw, kw, vw, wqkv);
        pack_qkv_b<<<(NLAY * QKVN + 255) / 256, 256>>>(qb, kb, vb, bqkv);
    }

    embed_kernel<<<SQ, 256>>>(ids, emb, pos, h);

    for (int l = 0; l < NLAY; l++) {
        const float* rw_l = rw + (size_t)l * HID * NEXP;
        const float* rb_l = rb + (size_t)l * NEXP;
        const float* fc1w_l = fc1w + (size_t)l * NEXP * HID * FFD;
        const float* fc1b_l = fc1b + (size_t)l * NEXP * FFD;
        const float* fc2w_l = fc2w + (size_t)l * NEXP * FFD * HID;
        const float* fc2b_l = fc2b + (size_t)l * NEXP * HID;

        // fused QKV projection: [1024,768] @ [768,1280], 64-wide N tiles
        {
            dim3 grid(QKVN / 64, SQ / 64);
            mma_gemm<false, false, false, 64><<<grid, 256, SMEM_N64>>>(
                h, wqkv + (size_t)l * HID * QKVN, bqkv + (size_t)l * QKVN,
                qkv, SQ, QKVN, HID, HID, QKVN, nullptr, nullptr, nullptr, 0, 0);
        }

        attn_kernel<<<dim3(SQ / 64, NHD), 256>>>(qkv, amask, res);
        ln_kernel<<<SQ, 256>>>(h, res, lng, lnb);

        zero_cnt_kernel<<<1, 32>>>(cnt);
        router_kernel<<<SQ, 256>>>(h, rw_l, rb_l, gates, texp, tlocal, cnt);
        assign_kernel<<<1, 256>>>(cnt, offs, perm, texp, tlocal, tslot, loads + l * NEXP);

        {   // fc1 + gelu (gathered rows), 128-wide tiles
            dim3 grid(FFD / 128, SQ / 64, NEXP);
            mma_gemm<true, true, true, 128><<<grid, 256, SMEM_N128>>>(
                h, fc1w_l, fc1b_l, h1, SQ, FFD, HID, HID, FFD,
                perm, offs, cnt, (size_t)HID * FFD, (size_t)FFD);
        }
        {   // fc2 (contiguous slots), 64-wide tiles for 2x parallelism
            dim3 grid(HID / 64, SQ / 64, NEXP);
            mma_gemm<false, true, false, 64><<<grid, 256, SMEM_N64>>>(
                h1, fc2w_l, fc2b_l, eo, SQ, HID, FFD, FFD, HID,
                nullptr, offs, cnt, (size_t)FFD * HID, (size_t)HID);
        }
        combine_kernel<<<SQ, 256>>>(eo, gates, tslot, res);
        ln_kernel<<<SQ, 256>>>(h, res, lng, lnb);
    }

    // final logits projection with 2xBF16 split; M-tiles fastest for L2 B reuse
    {
        dim3 grid(SQ / 64, (NVOC + 127) / 128);
        mma_gemm_bf16<<<grid, 256, GEMM_SMEM_BF>>>(
            h, ow, ob, out, SQ, NVOC, HID, HID, NVOC);
    }
    loss_kernel<<<1, 32>>>(loads, out + ((size_t)out_size - NLAY));
}

// round 14
// speedup vs baseline: 1.1369x; 1.1369x over previous
#include <cuda_runtime.h>
#include <math.h>
#include <stdint.h>

#define SQ   1024
#define HID  768
#define NHD  12
#define DH   64
#define NG   4
#define NLAY 4
#define NEXP 8
#define FFD  3072
#define NVOC 50257
#define QKVN 1280   // 768 + 256 + 256

// ---------------- scratch (device globals; no allocation) ----------------
__device__ float g_h[SQ * HID];
__device__ float g_res[SQ * HID];
__device__ float g_qkv[SQ * QKVN];
__device__ float g_wqkv[NLAY * HID * QKVN];
__device__ float g_bqkv[NLAY * QKVN];
__device__ float g_h1[2 * SQ * FFD];
__device__ float g_eo[2 * SQ * HID];
__device__ float g_gates[SQ * 2];
__device__ int   g_texp[SQ * 2];
__device__ int   g_tlocal[SQ * 2];
__device__ int   g_tslot[SQ * 2];
__device__ int   g_cnt[NEXP];
__device__ int   g_offs[NEXP];
__device__ int   g_perm[2 * SQ];
__device__ int   g_loads[NLAY * NEXP];

// ---------------- embedding ----------------
__global__ void embed_kernel(const int* __restrict__ ids,
                             const float* __restrict__ emb,
                             const float* __restrict__ pos,
                             float* __restrict__ h) {
    int s = blockIdx.x;
    int id = ids[s];
    for (int c = threadIdx.x; c < HID; c += blockDim.x)
        h[(size_t)s * HID + c] = emb[(size_t)id * HID + c] + pos[(size_t)s * HID + c];
}

// ---------------- pack qw|kw|vw -> wqkv ----------------
__global__ __launch_bounds__(256) void pack_qkv_w(
    const float* __restrict__ qw, const float* __restrict__ kw,
    const float* __restrict__ vw, float* __restrict__ wqkv)
{
    size_t idx = (size_t)blockIdx.x * 256 + threadIdx.x;
    if (idx >= (size_t)NLAY * HID * QKVN) return;
    int j = (int)(idx % QKVN);
    size_t li = idx / QKVN;            // l*HID + i
    float v;
    if (j < HID)            v = qw[li * HID + j];
    else if (j < HID + 256) v = kw[li * 256 + (j - HID)];
    else                    v = vw[li * 256 + (j - HID - 256)];
    wqkv[idx] = v;
}

__global__ void pack_qkv_b(const float* __restrict__ qb, const float* __restrict__ kb,
                           const float* __restrict__ vb, float* __restrict__ bqkv)
{
    int idx = blockIdx.x * 256 + threadIdx.x;
    if (idx >= NLAY * QKVN) return;
    int l = idx / QKVN, j = idx % QKVN;
    float v;
    if (j < HID)            v = qb[l * HID + j];
    else if (j < HID + 256) v = kb[l * 256 + (j - HID)];
    else                    v = vb[l * 256 + (j - HID - 256)];
    bqkv[idx] = v;
}

// ---------------- tf32 helpers ----------------
__device__ __forceinline__ uint32_t f2tf(float x) {
    uint32_t r;
    asm("cvt.rna.tf32.f32 %0, %1;" : "=r"(r) : "f"(x));
    return r;
}

__device__ __forceinline__ void mma_tf32(float c[4],
                                         uint32_t a0, uint32_t a1, uint32_t a2, uint32_t a3,
                                         uint32_t b0, uint32_t b1) {
    asm volatile(
        "mma.sync.aligned.m16n8k8.row.col.f32.tf32.tf32.f32 "
        "{%0,%1,%2,%3}, {%4,%5,%6,%7}, {%8,%9}, {%0,%1,%2,%3};"
        : "+f"(c[0]), "+f"(c[1]), "+f"(c[2]), "+f"(c[3])
        : "r"(a0), "r"(a1), "r"(a2), "r"(a3), "r"(b0), "r"(b1));
}

__device__ __forceinline__ uint4 tf_pack(float v0, float v4) {
    uint4 p;
    p.x = f2tf(v0);
    p.y = f2tf(v4);
    p.z = f2tf(v0 - __uint_as_float(p.x));
    p.w = f2tf(v4 - __uint_as_float(p.y));
    return p;
}

// ---------------- bf16 helpers ----------------
__device__ __forceinline__ uint32_t bf16pack2(float x0, float x1) {
    uint32_t r;
    asm("cvt.rn.bf16x2.f32 %0, %1, %2;" : "=r"(r) : "f"(x1), "f"(x0));
    return r;
}
__device__ __forceinline__ void bf16split2(float x0, float x1, uint32_t& hi, uint32_t& lo) {
    hi = bf16pack2(x0, x1);
    float h0 = __uint_as_float(hi << 16);
    float h1 = __uint_as_float(hi & 0xFFFF0000u);
    lo = bf16pack2(x0 - h0, x1 - h1);
}

__device__ __forceinline__ void mma_bf16(float c[4],
                                         uint32_t a0, uint32_t a1, uint32_t a2, uint32_t a3,
                                         uint32_t b0, uint32_t b1) {
    asm volatile(
        "mma.sync.aligned.m16n8k16.row.col.f32.bf16.bf16.f32 "
        "{%0,%1,%2,%3}, {%4,%5,%6,%7}, {%8,%9}, {%0,%1,%2,%3};"
        : "+f"(c[0]), "+f"(c[1]), "+f"(c[2]), "+f"(c[3])
        : "r"(a0), "r"(a1), "r"(a2), "r"(a3), "r"(b0), "r"(b1));
}

#define ASTG 576            // 64 rows * 9 uint4
#define BSTG 1152           // 128 rows * 9 uint4
#define GEMM_SMEM (2 * (ASTG + BSTG) * 16)   // double-buffered, bytes (55296)

// ---------------- 3xTF32 GEMM: 64(M)x128(N) tile, double-buffered, 2 blk/SM
template<bool GELU, bool EXPERT, bool GATHER>
__global__ __launch_bounds__(256, 2) void mma_gemm(
    const float* __restrict__ A, const float* __restrict__ B,
    const float* __restrict__ bias, float* __restrict__ C,
    int M, int N, int K, int lda, int ldc,
    const int* __restrict__ perm, const int* __restrict__ offs,
    const int* __restrict__ cnts, size_t strideB, size_t strideBias)
{
    extern __shared__ uint4 sm4[];
    uint4* AP = sm4;                 // [2][ASTG]
    uint4* BP = sm4 + 2 * ASTG;      // [2][BSTG]

    int mcount = M, base = 0;
    if (EXPERT) {
        int e = blockIdx.z;
        mcount = cnts[e];
        base   = offs[e];
        B     += (size_t)e * strideB;
        bias  += (size_t)e * strideBias;
    }
    int m0 = blockIdx.y * 64;
    if (m0 >= mcount) return;
    int n0 = blockIdx.x * 128;

    int tid = threadIdx.x, lane = tid & 31, warp = tid >> 5;
    int wm = (warp & 1) * 32;
    int wn = (warp >> 1) * 32;

    int aRow = tid >> 1;
    int aKK  = tid & 1;
    bool aprod = (tid < 128);
    bool aok = aprod && (m0 + aRow < mcount);
    const float* aptr = A;
    if (aok) {
        int phys = GATHER ? perm[base + m0 + aRow]
                          : (EXPERT ? base + m0 + aRow : m0 + aRow);
        aptr = A + (size_t)phys * (size_t)lda;
    }
    int bN   = tid & 127;
    int bKQ0 = tid >> 7;
    int gn   = n0 + bN;
    bool bok = (gn < N);

    float c[2][4][4];
#pragma unroll
    for (int i = 0; i < 2; i++)
#pragma unroll
        for (int j = 0; j < 4; j++)
#pragma unroll
            for (int q = 0; q < 4; q++) c[i][j][q] = 0.f;

    float stA[8], stB[8];

    if (aprod) {
        float4 v0 = make_float4(0.f,0.f,0.f,0.f), v1 = v0;
        if (aok) {
            v0 = *(const float4*)(aptr + aKK * 8);
            v1 = *(const float4*)(aptr + aKK * 8 + 4);
        }
        stA[0]=v0.x; stA[1]=v0.y; stA[2]=v0.z; stA[3]=v0.w;
        stA[4]=v1.x; stA[5]=v1.y; stA[6]=v1.z; stA[7]=v1.w;
    }
#pragma unroll
    for (int j = 0; j < 4; j++) {
        int kq = bKQ0 + 2 * j;
        int krow = (kq >> 2) * 8 + (kq & 3);
        float b0 = 0.f, b1 = 0.f;
        if (bok) {
            b0 = B[(size_t)krow * (size_t)N + gn];
            b1 = B[(size_t)(krow + 4) * (size_t)N + gn];
        }
        stB[j * 2] = b0; stB[j * 2 + 1] = b1;
    }
    if (aprod) {
#pragma unroll
        for (int q = 0; q < 4; q++)
            AP[aRow * 9 + aKK * 4 + q] = tf_pack(stA[q], stA[q + 4]);
    }
#pragma unroll
    for (int j = 0; j < 4; j++) {
        int kq = bKQ0 + 2 * j;
        BP[bN * 9 + kq] = tf_pack(stB[j * 2], stB[j * 2 + 1]);
    }
    __syncthreads();

    int buf = 0;
    for (int k0 = 0; k0 < K; k0 += 16) {
        bool has_next = (k0 + 16 < K);
        if (has_next) {
            if (aprod) {
                float4 v0 = make_float4(0.f,0.f,0.f,0.f), v1 = v0;
                if (aok) {
                    v0 = *(const float4*)(aptr + k0 + 16 + aKK * 8);
                    v1 = *(const float4*)(aptr + k0 + 16 + aKK * 8 + 4);
                }
                stA[0]=v0.x; stA[1]=v0.y; stA[2]=v0.z; stA[3]=v0.w;
                stA[4]=v1.x; stA[5]=v1.y; stA[6]=v1.z; stA[7]=v1.w;
            }
#pragma unroll
            for (int j = 0; j < 4; j++) {
                int kq = bKQ0 + 2 * j;
                int krow = k0 + 16 + (kq >> 2) * 8 + (kq & 3);
                float b0 = 0.f, b1 = 0.f;
                if (bok) {
                    b0 = B[(size_t)krow * (size_t)N + gn];
                    b1 = B[(size_t)(krow + 4) * (size_t)N + gn];
                }
                stB[j * 2] = b0; stB[j * 2 + 1] = b1;
            }
        }

        const uint4* APc = AP + buf * ASTG;
        const uint4* BPc = BP + buf * BSTG;
        int ra = lane >> 2;
        int q  = lane & 3;
#pragma unroll
        for (int kk = 0; kk < 2; kk++) {
            int kkq = kk * 4 + q;
            uint32_t aH[2][4], aL[2][4];
#pragma unroll
            for (int fm = 0; fm < 2; fm++) {
                int m = wm + fm * 16 + ra;
                uint4 f0 = APc[m * 9 + kkq];
                uint4 f1 = APc[(m + 8) * 9 + kkq];
                aH[fm][0] = f0.x; aH[fm][1] = f1.x;
                aH[fm][2] = f0.y; aH[fm][3] = f1.y;
                aL[fm][0] = f0.z; aL[fm][1] = f1.z;
                aL[fm][2] = f0.w; aL[fm][3] = f1.w;
            }
#pragma unroll
            for (int fn = 0; fn < 4; fn++) {
                int n = wn + fn * 8 + ra;
                uint4 fb = BPc[n * 9 + kkq];
#pragma unroll
                for (int fm = 0; fm < 2; fm++) {
                    mma_tf32(c[fm][fn], aL[fm][0], aL[fm][1], aL[fm][2], aL[fm][3], fb.x, fb.y);
                    mma_tf32(c[fm][fn], aH[fm][0], aH[fm][1], aH[fm][2], aH[fm][3], fb.z, fb.w);
                    mma_tf32(c[fm][fn], aH[fm][0], aH[fm][1], aH[fm][2], aH[fm][3], fb.x, fb.y);
                }
            }
        }

        if (has_next) {
            uint4* APn = AP + (buf ^ 1) * ASTG;
            uint4* BPn = BP + (buf ^ 1) * BSTG;
            if (aprod) {
#pragma unroll
                for (int qq = 0; qq < 4; qq++)
                    APn[aRow * 9 + aKK * 4 + qq] = tf_pack(stA[qq], stA[qq + 4]);
            }
#pragma unroll
            for (int j = 0; j < 4; j++) {
                int kq = bKQ0 + 2 * j;
                BPn[bN * 9 + kq] = tf_pack(stB[j * 2], stB[j * 2 + 1]);
            }
        }
        __syncthreads();
        buf ^= 1;
    }

#pragma unroll
    for (int fm = 0; fm < 2; fm++) {
#pragma unroll
        for (int half = 0; half < 2; half++) {
            int mrel = m0 + wm + fm * 16 + (lane >> 2) + half * 8;
            if (mrel >= mcount) continue;
            size_t crow = (size_t)(EXPERT ? base + mrel : mrel) * (size_t)ldc;
#pragma unroll
            for (int fn = 0; fn < 4; fn++) {
                int n = n0 + wn + fn * 8 + (lane & 3) * 2;
                float v0 = c[fm][fn][half * 2 + 0];
                float v1 = c[fm][fn][half * 2 + 1];
                if (n < N) {
                    float o = v0 + bias[n];
                    if (GELU) o = 0.5f * o * (1.f + erff(o * 0.70710678118654752f));
                    C[crow + n] = o;
                }
                if (n + 1 < N) {
                    float o = v1 + bias[n + 1];
                    if (GELU) o = 0.5f * o * (1.f + erff(o * 0.70710678118654752f));
                    C[crow + n + 1] = o;
                }
            }
        }
    }
}

// ---------------- 2xBF16 GEMM for the final logits projection --------------
// grid: (M-tiles, N-tiles) — M fastest so consecutive CTAs share the B slice (L2 reuse)
#define BA_STG (64 * 5)
#define BB_STG (128 * 5)
#define GEMM_SMEM_BF (2 * (BA_STG + BB_STG) * 16)   // 30720 bytes

__global__ __launch_bounds__(256, 2) void mma_gemm_bf16(
    const float* __restrict__ A, const float* __restrict__ B,
    const float* __restrict__ bias, float* __restrict__ C,
    int M, int N, int K, int lda, int ldc)
{
    extern __shared__ uint4 sm4[];
    uint4* AP = sm4;
    uint4* BP = sm4 + 2 * BA_STG;

    int m0 = blockIdx.x * 64;      // M fastest-varying for L2 B reuse
    int n0 = blockIdx.y * 128;

    int tid = threadIdx.x, lane = tid & 31, warp = tid >> 5;
    int wm = (warp & 1) * 32;
    int wn = (warp >> 1) * 32;

    int aRow = tid >> 1;
    int aH2  = tid & 1;
    bool aprod = (tid < 128);
    bool aok = aprod && (m0 + aRow < M);
    const float* aptr = A + (size_t)(m0 + aRow) * (size_t)lda;

    int bN = tid & 127;
    int bH = tid >> 7;
    int gn = n0 + bN;
    bool bok = (gn < N);

    float c[2][4][4];
#pragma unroll
    for (int i = 0; i < 2; i++)
#pragma unroll
        for (int j = 0; j < 4; j++)
#pragma unroll
            for (int q = 0; q < 4; q++) c[i][j][q] = 0.f;

    float sA[8], sB[8];

    if (aprod) {
        float4 v0 = make_float4(0.f,0.f,0.f,0.f), v1 = v0;
        if (aok) {
            v0 = *(const float4*)(aptr + aH2 * 4);
            v1 = *(const float4*)(aptr + aH2 * 4 + 8);
        }
        sA[0]=v0.x; sA[1]=v0.y; sA[2]=v0.z; sA[3]=v0.w;
        sA[4]=v1.x; sA[5]=v1.y; sA[6]=v1.z; sA[7]=v1.w;
    }
#pragma unroll
    for (int j = 0; j < 2; j++) {
        int q = 2 * bH + j;
        int k = 2 * q;
        float b0 = 0.f, b1 = 0.f, b2 = 0.f, b3 = 0.f;
        if (bok) {
            b0 = B[(size_t)k * N + gn];
            b1 = B[(size_t)(k + 1) * N + gn];
            b2 = B[(size_t)(k + 8) * N + gn];
            b3 = B[(size_t)(k + 9) * N + gn];
        }
        sB[j*4+0]=b0; sB[j*4+1]=b1; sB[j*4+2]=b2; sB[j*4+3]=b3;
    }
    if (aprod) {
#pragma unroll
        for (int j = 0; j < 2; j++) {
            uint4 p;
            bf16split2(sA[j*2+0], sA[j*2+1], p.x, p.z);
            bf16split2(sA[j*2+4], sA[j*2+5], p.y, p.w);
            AP[aRow * 5 + 2 * aH2 + j] = p;
        }
    }
#pragma unroll
    for (int j = 0; j < 2; j++) {
        uint4 p;
        bf16split2(sB[j*4+0], sB[j*4+1], p.x, p.z);
        bf16split2(sB[j*4+2], sB[j*4+3], p.y, p.w);
        BP[bN * 5 + 2 * bH + j] = p;
    }
    __syncthreads();

    int buf = 0;
    for (int k0 = 0; k0 < K; k0 += 16) {
        bool has_next = (k0 + 16 < K);
        if (has_next) {
            if (aprod) {
                float4 v0 = make_float4(0.f,0.f,0.f,0.f), v1 = v0;
                if (aok) {
                    v0 = *(const float4*)(aptr + k0 + 16 + aH2 * 4);
                    v1 = *(const float4*)(aptr + k0 + 16 + aH2 * 4 + 8);
                }
                sA[0]=v0.x; sA[1]=v0.y; sA[2]=v0.z; sA[3]=v0.w;
                sA[4]=v1.x; sA[5]=v1.y; sA[6]=v1.z; sA[7]=v1.w;
            }
#pragma unroll
            for (int j = 0; j < 2; j++) {
                int q = 2 * bH + j;
                int k = k0 + 16 + 2 * q;
                float b0 = 0.f, b1 = 0.f, b2 = 0.f, b3 = 0.f;
                if (bok) {
                    b0 = B[(size_t)k * N + gn];
                    b1 = B[(size_t)(k + 1) * N + gn];
                    b2 = B[(size_t)(k + 8) * N + gn];
                    b3 = B[(size_t)(k + 9) * N + gn];
                }
                sB[j*4+0]=b0; sB[j*4+1]=b1; sB[j*4+2]=b2; sB[j*4+3]=b3;
            }
        }

        const uint4* APc = AP + buf * BA_STG;
        const uint4* BPc = BP + buf * BB_STG;
        int ra = lane >> 2;
        int q  = lane & 3;
        uint32_t aHf[2][4], aLf[2][4];
#pragma unroll
        for (int fm = 0; fm < 2; fm++) {
            int m = wm + fm * 16 + ra;
            uint4 f0 = APc[m * 5 + q];
            uint4 f1 = APc[(m + 8) * 5 + q];
            aHf[fm][0] = f0.x; aHf[fm][1] = f1.x;
            aHf[fm][2] = f0.y; aHf[fm][3] = f1.y;
            aLf[fm][0] = f0.z; aLf[fm][1] = f1.z;
            aLf[fm][2] = f0.w; aLf[fm][3] = f1.w;
        }
#pragma unroll
        for (int fn = 0; fn < 4; fn++) {
            int n = wn + fn * 8 + ra;
            uint4 fb = BPc[n * 5 + q];
#pragma unroll
            for (int fm = 0; fm < 2; fm++) {
                mma_bf16(c[fm][fn], aLf[fm][0], aLf[fm][1], aLf[fm][2], aLf[fm][3], fb.x, fb.y);
                mma_bf16(c[fm][fn], aHf[fm][0], aHf[fm][1], aHf[fm][2], aHf[fm][3], fb.z, fb.w);
                mma_bf16(c[fm][fn], aHf[fm][0], aHf[fm][1], aHf[fm][2], aHf[fm][3], fb.x, fb.y);
            }
        }

        if (has_next) {
            uint4* APn = AP + (buf ^ 1) * BA_STG;
            uint4* BPn = BP + (buf ^ 1) * BB_STG;
            if (aprod) {
#pragma unroll
                for (int j = 0; j < 2; j++) {
                    uint4 p;
                    bf16split2(sA[j*2+0], sA[j*2+1], p.x, p.z);
                    bf16split2(sA[j*2+4], sA[j*2+5], p.y, p.w);
                    APn[aRow * 5 + 2 * aH2 + j] = p;
                }
            }
#pragma unroll
            for (int j = 0; j < 2; j++) {
                uint4 p;
                bf16split2(sB[j*4+0], sB[j*4+1], p.x, p.z);
                bf16split2(sB[j*4+2], sB[j*4+3], p.y, p.w);
                BPn[bN * 5 + 2 * bH + j] = p;
            }
        }
        __syncthreads();
        buf ^= 1;
    }

#pragma unroll
    for (int fm = 0; fm < 2; fm++) {
#pragma unroll
        for (int half = 0; half < 2; half++) {
            int mrel = m0 + wm + fm * 16 + (lane >> 2) + half * 8;
            if (mrel >= M) continue;
            size_t crow = (size_t)mrel * (size_t)ldc;
#pragma unroll
            for (int fn = 0; fn < 4; fn++) {
                int n = n0 + wn + fn * 8 + (lane & 3) * 2;
                if (n < N)     C[crow + n]     = c[fm][fn][half * 2 + 0] + bias[n];
                if (n + 1 < N) C[crow + n + 1] = c[fm][fn][half * 2 + 1] + bias[n + 1];
            }
        }
    }
}

// ---------------- flash-style GQA attention (fp32, reads combined QKV) ----------------
__global__ __launch_bounds__(256) void attn_kernel(
    const float* __restrict__ qkv, const int* __restrict__ amask,
    float* __restrict__ ao)
{
    const float SCALE = 0.125f;
    int head = blockIdx.y;
    int g    = head / (NHD / NG);
    int q0   = blockIdx.x * 64;

    __shared__ float QsT[64][68];
    __shared__ float KsT[64][33];
    __shared__ float Vs [32][68];
    __shared__ float PsT[32][68];
    __shared__ float Mk [32];

    int tid = threadIdx.x;
#pragma unroll
    for (int i = 0; i < 4; i++) {
        int idx = tid + i * 256;
        int r = idx >> 4;
        int dseg = (idx & 15) * 4;
        float4 qv = *(const float4*)(qkv + (size_t)(q0 + r) * QKVN + head * 64 + dseg);
        QsT[dseg + 0][r] = qv.x; QsT[dseg + 1][r] = qv.y;
        QsT[dseg + 2][r] = qv.z; QsT[dseg + 3][r] = qv.w;
    }

    int rg = tid >> 4, kg = tid & 15;
    int r0 = rg * 4, d0 = kg * 4, j0 = kg * 2;

    float acc[4][4] = {};
    float m[4], l[4];
#pragma unroll
    for (int i = 0; i < 4; i++) { m[i] = -3.0e38f; l[i] = 0.f; }

    for (int kc = 0; kc < 32; kc++) {
        int kbase = kc * 32;
#pragma unroll
        for (int i = 0; i < 2; i++) {
            int idx = tid + i * 256;
            int kk = idx >> 4;
            int dseg = (idx & 15) * 4;
            float4 kv = *(const float4*)(qkv + (size_t)(kbase + kk) * QKVN + HID + g * 64 + dseg);
            KsT[dseg + 0][kk] = kv.x; KsT[dseg + 1][kk] = kv.y;
            KsT[dseg + 2][kk] = kv.z; KsT[dseg + 3][kk] = kv.w;
            float4 vv = *(const float4*)(qkv + (size_t)(kbase + kk) * QKVN + HID + 256 + g * 64 + dseg);
            *(float4*)&Vs[kk][dseg] = vv;
        }
        if (tid < 32) Mk[tid] = (amask[kbase + tid] == 0) ? -3.0e38f : 0.f;
        __syncthreads();

        float s0[4] = {}, s1[4] = {};
#pragma unroll
        for (int d = 0; d < 64; d++) {
            float4 a = *(const float4*)&QsT[d][r0];
            float b0 = KsT[d][j0], b1 = KsT[d][j0 + 1];
            s0[0] += a.x * b0; s1[0] += a.x * b1;
            s0[1] += a.y * b0; s1[1] += a.y * b1;
            s0[2] += a.z * b0; s1[2] += a.z * b1;
            s0[3] += a.w * b0; s1[3] += a.w * b1;
        }
        float mk0 = Mk[j0], mk1 = Mk[j0 + 1];
        float cm[4];
#pragma unroll
        for (int i = 0; i < 4; i++) {
            s0[i] = s0[i] * SCALE + mk0;
            s1[i] = s1[i] * SCALE + mk1;
            cm[i] = fmaxf(s0[i], s1[i]);
        }
#pragma unroll
        for (int o = 1; o < 16; o <<= 1)
#pragma unroll
            for (int i = 0; i < 4; i++)
                cm[i] = fmaxf(cm[i], __shfl_xor_sync(0xffffffffu, cm[i], o));

        float p0[4], p1[4], csum[4];
#pragma unroll
        for (int i = 0; i < 4; i++) {
            float nm = fmaxf(m[i], cm[i]);
            float alpha = expf(m[i] - nm);
            m[i] = nm;
            p0[i] = expf(s0[i] - nm);
            p1[i] = expf(s1[i] - nm);
            csum[i] = p0[i] + p1[i];
            l[i] *= alpha;
#pragma unroll
            for (int j = 0; j < 4; j++) acc[i][j] *= alpha;
        }
#pragma unroll
        for (int o = 1; o < 16; o <<= 1)
#pragma unroll
            for (int i = 0; i < 4; i++)
                csum[i] += __shfl_xor_sync(0xffffffffu, csum[i], o);
#pragma unroll
        for (int i = 0; i < 4; i++) l[i] += csum[i];

#pragma unroll
        for (int i = 0; i < 4; i++) {
            PsT[j0][r0 + i]     = p0[i];
            PsT[j0 + 1][r0 + i] = p1[i];
        }
        __syncthreads();

#pragma unroll
        for (int key = 0; key < 32; key++) {
            float4 pv = *(const float4*)&PsT[key][r0];
            float4 vv = *(const float4*)&Vs[key][d0];
            acc[0][0] += pv.x * vv.x; acc[0][1] += pv.x * vv.y; acc[0][2] += pv.x * vv.z; acc[0][3] += pv.x * vv.w;
            acc[1][0] += pv.y * vv.x; acc[1][1] += pv.y * vv.y; acc[1][2] += pv.y * vv.z; acc[1][3] += pv.y * vv.w;
            acc[2][0] += pv.z * vv.x; acc[2][1] += pv.z * vv.y; acc[2][2] += pv.z * vv.z; acc[2][3] += pv.z * vv.w;
            acc[3][0] += pv.w * vv.x; acc[3][1] += pv.w * vv.y; acc[3][2] += pv.w * vv.z; acc[3][3] += pv.w * vv.w;
        }
        __syncthreads();
    }

#pragma unroll
    for (int i = 0; i < 4; i++) {
        float inv = 1.f / l[i];
        float4 o;
        o.x = acc[i][0] * inv; o.y = acc[i][1] * inv;
        o.z = acc[i][2] * inv; o.w = acc[i][3] * inv;
        *(float4*)(ao + (size_t)(q0 + r0 + i) * HID + head * 64 + d0) = o;
    }
}

// ---------------- layernorm: h = LN(h + res) ----------------
__global__ __launch_bounds__(256) void ln_kernel(float* __restrict__ h,
                                                 const float* __restrict__ res,
                                                 const float* __restrict__ gam,
                                                 const float* __restrict__ bet) {
    int row = blockIdx.x;
    __shared__ float xbuf[HID];
    __shared__ float red[256];
    int tid = threadIdx.x;
    float lsum = 0.f;
    for (int c = tid; c < HID; c += 256) {
        float v = h[(size_t)row * HID + c] + res[(size_t)row * HID + c];
        xbuf[c] = v;
        lsum += v;
    }
    red[tid] = lsum; __syncthreads();
    for (int s = 128; s > 0; s >>= 1) { if (tid < s) red[tid] += red[tid + s]; __syncthreads(); }
    float mean = red[0] / (float)HID;
    __syncthreads();
    float lvar = 0.f;
    for (int c = tid; c < HID; c += 256) { float d = xbuf[c] - mean; lvar += d * d; }
    red[tid] = lvar; __syncthreads();
    for (int s = 128; s > 0; s >>= 1) { if (tid < s) red[tid] += red[tid + s]; __syncthreads(); }
    float rstd = rsqrtf(red[0] / (float)HID + 1e-5f);
    for (int c = tid; c < HID; c += 256)
        h[(size_t)row * HID + c] = (xbuf[c] - mean) * rstd * gam[c] + bet[c];
}

// ---------------- router: top-2 gating ----------------
__global__ __launch_bounds__(256) void router_kernel(
    const float* __restrict__ h, const float* __restrict__ rw,
    const float* __restrict__ rb, float* __restrict__ gates,
    int* __restrict__ texp, int* __restrict__ tlocal, int* __restrict__ cnt)
{
    int t = blockIdx.x;
    int tid = threadIdx.x;
    int e = tid >> 5, lane = tid & 31;
    float sum = 0.f;
    for (int i = lane; i < HID; i += 32)
        sum += h[(size_t)t * HID + i] * rw[i * NEXP + e];
#pragma unroll
    for (int o = 16; o > 0; o >>= 1) sum += __shfl_down_sync(0xffffffffu, sum, o);
    __shared__ float logits[NEXP];
    if (lane == 0) logits[e] = sum + rb[e];
    __syncthreads();
    if (tid == 0) {
        float mx = logits[0];
        for (int i = 1; i < NEXP; i++) mx = fmaxf(mx, logits[i]);
        float ex[NEXP], ssum = 0.f;
        for (int i = 0; i < NEXP; i++) { ex[i] = expf(logits[i] - mx); ssum += ex[i]; }
        float p[NEXP];
        for (int i = 0; i < NEXP; i++) p[i] = ex[i] / ssum;
        int i0 = 0;
        for (int i = 1; i < NEXP; i++) if (p[i] > p[i0]) i0 = i;
        int i1 = (i0 == 0) ? 1 : 0;
        for (int i = 0; i < NEXP; i++) if (i != i0 && p[i] > p[i1]) i1 = i;
        float b = expf(p[i1] - p[i0]);
        float g0 = 1.f / (1.f + b);
        float g1 = b / (1.f + b);
        gates[t * 2] = g0; gates[t * 2 + 1] = g1;
        texp[t * 2] = i0; texp[t * 2 + 1] = i1;
        tlocal[t * 2]     = atomicAdd(&cnt[i0], 1);
        tlocal[t * 2 + 1] = atomicAdd(&cnt[i1], 1);
    }
}

__global__ void zero_cnt_kernel(int* c) { if (threadIdx.x < NEXP) c[threadIdx.x] = 0; }

__global__ __launch_bounds__(256) void assign_kernel(
    const int* __restrict__ cnt, int* __restrict__ offs, int* __restrict__ perm,
    const int* __restrict__ texp, const int* __restrict__ tlocal,
    int* __restrict__ tslot, int* __restrict__ loads)
{
    __shared__ int so[NEXP];
    if (threadIdx.x == 0) {
        int acc = 0;
        for (int e = 0; e < NEXP; e++) {
            so[e] = acc; offs[e] = acc; loads[e] = cnt[e]; acc += cnt[e];
        }
    }
    __syncthreads();
    for (int i = threadIdx.x; i < 2 * SQ; i += blockDim.x) {
        int t = i >> 1;
        int slot = so[texp[i]] + tlocal[i];
        perm[slot] = t;
        tslot[i] = slot;
    }
}

__global__ __launch_bounds__(256) void combine_kernel(
    const float* __restrict__ eo, const float* __restrict__ gates,
    const int* __restrict__ tslot, float* __restrict__ res)
{
    int t = blockIdx.x;
    int s0 = tslot[t * 2], s1 = tslot[t * 2 + 1];
    float g0 = gates[t * 2], g1 = gates[t * 2 + 1];
    for (int c = threadIdx.x; c < HID; c += 256)
        res[(size_t)t * HID + c] = g0 * eo[(size_t)s0 * HID + c] + g1 * eo[(size_t)s1 * HID + c];
}

__global__ void loss_kernel(const int* __restrict__ loads, float* __restrict__ out) {
    int l = threadIdx.x;
    if (l < NLAY) {
        float mean = (float)(2 * SQ) / (float)NEXP;
        float var = 0.f;
        for (int e = 0; e < NEXP; e++) {
            float d = (float)loads[l * NEXP + e] - mean;
            var += d * d;
        }
        var /= (float)(NEXP - 1);
        out[l] = var / (mean * mean);
    }
}

// ---------------- host launch ----------------
static void launch_gemm(const float* A, const float* B, const float* bias,
                        float* C, int M, int N, int K, int lda, int ldc) {
    dim3 grid((N + 127) / 128, (M + 63) / 64);
    mma_gemm<false, false, false><<<grid, 256, GEMM_SMEM>>>(
        A, B, bias, C, M, N, K, lda, ldc, nullptr, nullptr, nullptr, 0, 0);
}

extern "C" void kernel_launch(void* const* d_in, const int* in_sizes, int n_in,
                              void* d_out, int out_size) {
    const int*   ids   = (const int*)d_in[0];
    const int*   amask = (const int*)d_in[1];
    const float* emb   = (const float*)d_in[2];
    const float* pos   = (const float*)d_in[3];
    const float* qw    = (const float*)d_in[4];
    const float* qb    = (const float*)d_in[5];
    const float* kw    = (const float*)d_in[6];
    const float* kb    = (const float*)d_in[7];
    const float* vw    = (const float*)d_in[8];
    const float* vb    = (const float*)d_in[9];
    const float* rw    = (const float*)d_in[10];
    const float* rb    = (const float*)d_in[11];
    const float* fc1w  = (const float*)d_in[12];
    const float* fc1b  = (const float*)d_in[13];
    const float* fc2w  = (const float*)d_in[14];
    const float* fc2b  = (const float*)d_in[15];
    const float* lng   = (const float*)d_in[16];
    const float* lnb   = (const float*)d_in[17];
    const float* ow    = (const float*)d_in[18];
    const float* ob    = (const float*)d_in[19];
    float* out = (float*)d_out;

    cudaFuncSetAttribute(mma_gemm<false, false, false>,
                         cudaFuncAttributeMaxDynamicSharedMemorySize, GEMM_SMEM);
    cudaFuncSetAttribute(mma_gemm<true, true, true>,
                         cudaFuncAttributeMaxDynamicSharedMemorySize, GEMM_SMEM);
    cudaFuncSetAttribute(mma_gemm<false, true, false>,
                         cudaFuncAttributeMaxDynamicSharedMemorySize, GEMM_SMEM);
    cudaFuncSetAttribute(mma_gemm_bf16,
                         cudaFuncAttributeMaxDynamicSharedMemorySize, GEMM_SMEM_BF);

    float *h, *res, *qkv, *wqkv, *bqkv, *h1, *eo, *gates;
    int *texp, *tlocal, *tslot, *cnt, *offs, *perm, *loads;
    cudaGetSymbolAddress((void**)&h, g_h);
    cudaGetSymbolAddress((void**)&res, g_res);
    cudaGetSymbolAddress((void**)&qkv, g_qkv);
    cudaGetSymbolAddress((void**)&wqkv, g_wqkv);
    cudaGetSymbolAddress((void**)&bqkv, g_bqkv);
    cudaGetSymbolAddress((void**)&h1, g_h1);
    cudaGetSymbolAddress((void**)&eo, g_eo);
    cudaGetSymbolAddress((void**)&gates, g_gates);
    cudaGetSymbolAddress((void**)&texp, g_texp);
    cudaGetSymbolAddress((void**)&tlocal, g_tlocal);
    cudaGetSymbolAddress((void**)&tslot, g_tslot);
    cudaGetSymbolAddress((void**)&cnt, g_cnt);
    cudaGetSymbolAddress((void**)&offs, g_offs);
    cudaGetSymbolAddress((void**)&perm, g_perm);
    cudaGetSymbolAddress((void**)&loads, g_loads);

    {
        size_t tot = (size_t)NLAY * HID * QKVN;
        pack_qkv_w<<<(unsigned)((tot + 255) / 256), 256>>>(qw, kw, vw, wqkv);
        pack_qkv_b<<<(NLAY * QKVN + 255) / 256, 256>>>(qb, kb, vb, bqkv);
    }

    embed_kernel<<<SQ, 256>>>(ids, emb, pos, h);

    for (int l = 0; l < NLAY; l++) {
        const float* rw_l = rw + (size_t)l * HID * NEXP;
        const float* rb_l = rb + (size_t)l * NEXP;
        const float* fc1w_l = fc1w + (size_t)l * NEXP * HID * FFD;
        const float* fc1b_l = fc1b + (size_t)l * NEXP * FFD;
        const float* fc2w_l = fc2w + (size_t)l * NEXP * FFD * HID;
        const float* fc2b_l = fc2b + (size_t)l * NEXP * HID;

        // fused QKV projection: [1024,768] @ [768,1280]
        launch_gemm(h, wqkv + (size_t)l * HID * QKVN, bqkv + (size_t)l * QKVN,
                    qkv, SQ, QKVN, HID, HID, QKVN);

        attn_kernel<<<dim3(SQ / 64, NHD), 256>>>(qkv, amask, res);
        ln_kernel<<<SQ, 256>>>(h, res, lng, lnb);

        zero_cnt_kernel<<<1, 32>>>(cnt);
        router_kernel<<<SQ, 256>>>(h, rw_l, rb_l, gates, texp, tlocal, cnt);
        assign_kernel<<<1, 256>>>(cnt, offs, perm, texp, tlocal, tslot, loads + l * NEXP);

        {   // fc1 + gelu (gathered rows)
            dim3 grid(FFD / 128, SQ / 64, NEXP);
            mma_gemm<true, true, true><<<grid, 256, GEMM_SMEM>>>(
                h, fc1w_l, fc1b_l, h1, SQ, FFD, HID, HID, FFD,
                perm, offs, cnt, (size_t)HID * FFD, (size_t)FFD);
        }
        {   // fc2 (contiguous slots)
            dim3 grid(HID / 128, SQ / 64, NEXP);
            mma_gemm<false, true, false><<<grid, 256, GEMM_SMEM>>>(
                h1, fc2w_l, fc2b_l, eo, SQ, HID, FFD, FFD, HID,
                nullptr, offs, cnt, (size_t)FFD * HID, (size_t)HID);
        }
        combine_kernel<<<SQ, 256>>>(eo, gates, tslot, res);
        ln_kernel<<<SQ, 256>>>(h, res, lng, lnb);
    }

    // final logits projection with 2xBF16 split; M-tiles fastest for L2 B reuse
    {
        dim3 grid(SQ / 64, (NVOC + 127) / 128);
        mma_gemm_bf16<<<grid, 256, GEMM_SMEM_BF>>>(
            h, ow, ob, out, SQ, NVOC, HID, HID, NVOC);
    }
    loss_kernel<<<1, 32>>>(loads, out + ((size_t)out_size - NLAY));
}

// round 15
// speedup vs baseline: 1.1528x; 1.0140x over previous
#include <cuda_runtime.h>
#include <math.h>
#include <stdint.h>

#define SQ   1024
#define HID  768
#define NHD  12
#define DH   64
#define NG   4
#define NLAY 4
#define NEXP 8
#define FFD  3072
#define NVOC 50257
#define QKVN 1280   // 768 + 256 + 256

// ---------------- scratch (device globals; no allocation) ----------------
__device__ float g_h[SQ * HID];
__device__ float g_res[SQ * HID];
__device__ float g_qkv[SQ * QKVN];
__device__ float g_wqkv[NLAY * HID * QKVN];
__device__ float g_bqkv[NLAY * QKVN];
__device__ float g_h1[2 * SQ * FFD];
__device__ float g_eo[2 * SQ * HID];
__device__ float g_gates[SQ * 2];
__device__ int   g_texp[SQ * 2];
__device__ int   g_tlocal[SQ * 2];
__device__ int   g_tslot[SQ * 2];
__device__ int   g_cnt[NEXP];
__device__ int   g_offs[NEXP];
__device__ int   g_perm[2 * SQ];
__device__ int   g_loads[NLAY * NEXP];

// ---------------- embedding ----------------
__global__ void embed_kernel(const int* __restrict__ ids,
                             const float* __restrict__ emb,
                             const float* __restrict__ pos,
                             float* __restrict__ h) {
    int s = blockIdx.x;
    int id = ids[s];
    for (int c = threadIdx.x; c < HID; c += blockDim.x)
        h[(size_t)s * HID + c] = emb[(size_t)id * HID + c] + pos[(size_t)s * HID + c];
}

// ---------------- pack qw|kw|vw -> wqkv ----------------
__global__ __launch_bounds__(256) void pack_qkv_w(
    const float* __restrict__ qw, const float* __restrict__ kw,
    const float* __restrict__ vw, float* __restrict__ wqkv)
{
    size_t idx = (size_t)blockIdx.x * 256 + threadIdx.x;
    if (idx >= (size_t)NLAY * HID * QKVN) return;
    int j = (int)(idx % QKVN);
    size_t li = idx / QKVN;            // l*HID + i
    float v;
    if (j < HID)            v = qw[li * HID + j];
    else if (j < HID + 256) v = kw[li * 256 + (j - HID)];
    else                    v = vw[li * 256 + (j - HID - 256)];
    wqkv[idx] = v;
}

__global__ void pack_qkv_b(const float* __restrict__ qb, const float* __restrict__ kb,
                           const float* __restrict__ vb, float* __restrict__ bqkv)
{
    int idx = blockIdx.x * 256 + threadIdx.x;
    if (idx >= NLAY * QKVN) return;
    int l = idx / QKVN, j = idx % QKVN;
    float v;
    if (j < HID)            v = qb[l * HID + j];
    else if (j < HID + 256) v = kb[l * 256 + (j - HID)];
    else                    v = vb[l * 256 + (j - HID - 256)];
    bqkv[idx] = v;
}

// ---------------- tf32 helpers ----------------
__device__ __forceinline__ uint32_t f2tf(float x) {
    uint32_t r;
    asm("cvt.rna.tf32.f32 %0, %1;" : "=r"(r) : "f"(x));
    return r;
}

__device__ __forceinline__ void mma_tf32(float c[4],
                                         uint32_t a0, uint32_t a1, uint32_t a2, uint32_t a3,
                                         uint32_t b0, uint32_t b1) {
    asm volatile(
        "mma.sync.aligned.m16n8k8.row.col.f32.tf32.tf32.f32 "
        "{%0,%1,%2,%3}, {%4,%5,%6,%7}, {%8,%9}, {%0,%1,%2,%3};"
        : "+f"(c[0]), "+f"(c[1]), "+f"(c[2]), "+f"(c[3])
        : "r"(a0), "r"(a1), "r"(a2), "r"(a3), "r"(b0), "r"(b1));
}

__device__ __forceinline__ uint4 tf_pack(float v0, float v4) {
    uint4 p;
    p.x = f2tf(v0);
    p.y = f2tf(v4);
    p.z = f2tf(v0 - __uint_as_float(p.x));
    p.w = f2tf(v4 - __uint_as_float(p.y));
    return p;
}

// ---------------- bf16 helpers ----------------
__device__ __forceinline__ uint32_t bf16pack2(float x0, float x1) {
    uint32_t r;
    asm("cvt.rn.bf16x2.f32 %0, %1, %2;" : "=r"(r) : "f"(x1), "f"(x0));
    return r;
}
__device__ __forceinline__ void bf16split2(float x0, float x1, uint32_t& hi, uint32_t& lo) {
    hi = bf16pack2(x0, x1);
    float h0 = __uint_as_float(hi << 16);
    float h1 = __uint_as_float(hi & 0xFFFF0000u);
    lo = bf16pack2(x0 - h0, x1 - h1);
}

__device__ __forceinline__ void mma_bf16(float c[4],
                                         uint32_t a0, uint32_t a1, uint32_t a2, uint32_t a3,
                                         uint32_t b0, uint32_t b1) {
    asm volatile(
        "mma.sync.aligned.m16n8k16.row.col.f32.bf16.bf16.f32 "
        "{%0,%1,%2,%3}, {%4,%5,%6,%7}, {%8,%9}, {%0,%1,%2,%3};"
        : "+f"(c[0]), "+f"(c[1]), "+f"(c[2]), "+f"(c[3])
        : "r"(a0), "r"(a1), "r"(a2), "r"(a3), "r"(b0), "r"(b1));
}

#define ASTG 576            // 64 rows * 9 uint4
#define BSTG 1152           // 128 rows * 9 uint4
#define GEMM_SMEM (2 * (ASTG + BSTG) * 16)   // double-buffered, bytes (55296)

// ---------------- 3xTF32 GEMM: 64(M)x128(N) tile, double-buffered, 2 blk/SM
template<bool GELU, bool EXPERT, bool GATHER>
__global__ __launch_bounds__(256, 2) void mma_gemm(
    const float* __restrict__ A, const float* __restrict__ B,
    const float* __restrict__ bias, float* __restrict__ C,
    int M, int N, int K, int lda, int ldc,
    const int* __restrict__ perm, const int* __restrict__ offs,
    const int* __restrict__ cnts, size_t strideB, size_t strideBias)
{
    extern __shared__ uint4 sm4[];
    uint4* AP = sm4;                 // [2][ASTG]
    uint4* BP = sm4 + 2 * ASTG;      // [2][BSTG]

    int mcount = M, base = 0;
    if (EXPERT) {
        int e = blockIdx.z;
        mcount = cnts[e];
        base   = offs[e];
        B     += (size_t)e * strideB;
        bias  += (size_t)e * strideBias;
    }
    int m0 = blockIdx.y * 64;
    if (m0 >= mcount) return;
    int n0 = blockIdx.x * 128;

    int tid = threadIdx.x, lane = tid & 31, warp = tid >> 5;
    int wm = (warp & 1) * 32;
    int wn = (warp >> 1) * 32;

    int aRow = tid >> 1;
    int aKK  = tid & 1;
    bool aprod = (tid < 128);
    bool aok = aprod && (m0 + aRow < mcount);
    const float* aptr = A;
    if (aok) {
        int phys = GATHER ? perm[base + m0 + aRow]
                          : (EXPERT ? base + m0 + aRow : m0 + aRow);
        aptr = A + (size_t)phys * (size_t)lda;
    }
    int bN   = tid & 127;
    int bKQ0 = tid >> 7;
    int gn   = n0 + bN;
    bool bok = (gn < N);

    float c[2][4][4];
#pragma unroll
    for (int i = 0; i < 2; i++)
#pragma unroll
        for (int j = 0; j < 4; j++)
#pragma unroll
            for (int q = 0; q < 4; q++) c[i][j][q] = 0.f;

    float stA[8], stB[8];

    if (aprod) {
        float4 v0 = make_float4(0.f,0.f,0.f,0.f), v1 = v0;
        if (aok) {
            v0 = *(const float4*)(aptr + aKK * 8);
            v1 = *(const float4*)(aptr + aKK * 8 + 4);
        }
        stA[0]=v0.x; stA[1]=v0.y; stA[2]=v0.z; stA[3]=v0.w;
        stA[4]=v1.x; stA[5]=v1.y; stA[6]=v1.z; stA[7]=v1.w;
    }
#pragma unroll
    for (int j = 0; j < 4; j++) {
        int kq = bKQ0 + 2 * j;
        int krow = (kq >> 2) * 8 + (kq & 3);
        float b0 = 0.f, b1 = 0.f;
        if (bok) {
            b0 = B[(size_t)krow * (size_t)N + gn];
            b1 = B[(size_t)(krow + 4) * (size_t)N + gn];
        }
        stB[j * 2] = b0; stB[j * 2 + 1] = b1;
    }
    if (aprod) {
#pragma unroll
        for (int q = 0; q < 4; q++)
            AP[aRow * 9 + aKK * 4 + q] = tf_pack(stA[q], stA[q + 4]);
    }
#pragma unroll
    for (int j = 0; j < 4; j++) {
        int kq = bKQ0 + 2 * j;
        BP[bN * 9 + kq] = tf_pack(stB[j * 2], stB[j * 2 + 1]);
    }
    __syncthreads();

    int buf = 0;
    for (int k0 = 0; k0 < K; k0 += 16) {
        bool has_next = (k0 + 16 < K);
        if (has_next) {
            if (aprod) {
                float4 v0 = make_float4(0.f,0.f,0.f,0.f), v1 = v0;
                if (aok) {
                    v0 = *(const float4*)(aptr + k0 + 16 + aKK * 8);
                    v1 = *(const float4*)(aptr + k0 + 16 + aKK * 8 + 4);
                }
                stA[0]=v0.x; stA[1]=v0.y; stA[2]=v0.z; stA[3]=v0.w;
                stA[4]=v1.x; stA[5]=v1.y; stA[6]=v1.z; stA[7]=v1.w;
            }
#pragma unroll
            for (int j = 0; j < 4; j++) {
                int kq = bKQ0 + 2 * j;
                int krow = k0 + 16 + (kq >> 2) * 8 + (kq & 3);
                float b0 = 0.f, b1 = 0.f;
                if (bok) {
                    b0 = B[(size_t)krow * (size_t)N + gn];
                    b1 = B[(size_t)(krow + 4) * (size_t)N + gn];
                }
                stB[j * 2] = b0; stB[j * 2 + 1] = b1;
            }
        }

        const uint4* APc = AP + buf * ASTG;
        const uint4* BPc = BP + buf * BSTG;
        int ra = lane >> 2;
        int q  = lane & 3;
#pragma unroll
        for (int kk = 0; kk < 2; kk++) {
            int kkq = kk * 4 + q;
            uint32_t aH[2][4], aL[2][4];
#pragma unroll
            for (int fm = 0; fm < 2; fm++) {
                int m = wm + fm * 16 + ra;
                uint4 f0 = APc[m * 9 + kkq];
                uint4 f1 = APc[(m + 8) * 9 + kkq];
                aH[fm][0] = f0.x; aH[fm][1] = f1.x;
                aH[fm][2] = f0.y; aH[fm][3] = f1.y;
                aL[fm][0] = f0.z; aL[fm][1] = f1.z;
                aL[fm][2] = f0.w; aL[fm][3] = f1.w;
            }
            // software-pipelined B fragments: prefetch next before MMAs
            uint4 fb = BPc[(wn + ra) * 9 + kkq];
#pragma unroll
            for (int fn = 0; fn < 4; fn++) {
                uint4 fbn = fb;
                if (fn < 3) fbn = BPc[(wn + (fn + 1) * 8 + ra) * 9 + kkq];
#pragma unroll
                for (int fm = 0; fm < 2; fm++) {
                    mma_tf32(c[fm][fn], aL[fm][0], aL[fm][1], aL[fm][2], aL[fm][3], fb.x, fb.y);
                    mma_tf32(c[fm][fn], aH[fm][0], aH[fm][1], aH[fm][2], aH[fm][3], fb.z, fb.w);
                    mma_tf32(c[fm][fn], aH[fm][0], aH[fm][1], aH[fm][2], aH[fm][3], fb.x, fb.y);
                }
                fb = fbn;
            }
        }

        if (has_next) {
            uint4* APn = AP + (buf ^ 1) * ASTG;
            uint4* BPn = BP + (buf ^ 1) * BSTG;
            if (aprod) {
#pragma unroll
                for (int qq = 0; qq < 4; qq++)
                    APn[aRow * 9 + aKK * 4 + qq] = tf_pack(stA[qq], stA[qq + 4]);
            }
#pragma unroll
            for (int j = 0; j < 4; j++) {
                int kq = bKQ0 + 2 * j;
                BPn[bN * 9 + kq] = tf_pack(stB[j * 2], stB[j * 2 + 1]);
            }
        }
        __syncthreads();
        buf ^= 1;
    }

#pragma unroll
    for (int fm = 0; fm < 2; fm++) {
#pragma unroll
        for (int half = 0; half < 2; half++) {
            int mrel = m0 + wm + fm * 16 + (lane >> 2) + half * 8;
            if (mrel >= mcount) continue;
            size_t crow = (size_t)(EXPERT ? base + mrel : mrel) * (size_t)ldc;
#pragma unroll
            for (int fn = 0; fn < 4; fn++) {
                int n = n0 + wn + fn * 8 + (lane & 3) * 2;
                float v0 = c[fm][fn][half * 2 + 0];
                float v1 = c[fm][fn][half * 2 + 1];
                if (n < N) {
                    float o = v0 + bias[n];
                    if (GELU) o = 0.5f * o * (1.f + erff(o * 0.70710678118654752f));
                    C[crow + n] = o;
                }
                if (n + 1 < N) {
                    float o = v1 + bias[n + 1];
                    if (GELU) o = 0.5f * o * (1.f + erff(o * 0.70710678118654752f));
                    C[crow + n + 1] = o;
                }
            }
        }
    }
}

// ---------------- 2xBF16 GEMM for the final logits projection --------------
#define BA_STG (64 * 5)
#define BB_STG (128 * 5)
#define GEMM_SMEM_BF (2 * (BA_STG + BB_STG) * 16)   // 30720 bytes

__global__ __launch_bounds__(256, 2) void mma_gemm_bf16(
    const float* __restrict__ A, const float* __restrict__ B,
    const float* __restrict__ bias, float* __restrict__ C,
    int M, int N, int K, int lda, int ldc)
{
    extern __shared__ uint4 sm4[];
    uint4* AP = sm4;
    uint4* BP = sm4 + 2 * BA_STG;

    int m0 = blockIdx.x * 64;      // M fastest-varying for L2 B reuse
    int n0 = blockIdx.y * 128;

    int tid = threadIdx.x, lane = tid & 31, warp = tid >> 5;
    int wm = (warp & 1) * 32;
    int wn = (warp >> 1) * 32;

    int aRow = tid >> 1;
    int aH2  = tid & 1;
    bool aprod = (tid < 128);
    bool aok = aprod && (m0 + aRow < M);
    const float* aptr = A + (size_t)(m0 + aRow) * (size_t)lda;

    int bN = tid & 127;
    int bH = tid >> 7;
    int gn = n0 + bN;
    bool bok = (gn < N);

    float c[2][4][4];
#pragma unroll
    for (int i = 0; i < 2; i++)
#pragma unroll
        for (int j = 0; j < 4; j++)
#pragma unroll
            for (int q = 0; q < 4; q++) c[i][j][q] = 0.f;

    float sA[8], sB[8];

    if (aprod) {
        float4 v0 = make_float4(0.f,0.f,0.f,0.f), v1 = v0;
        if (aok) {
            v0 = *(const float4*)(aptr + aH2 * 4);
            v1 = *(const float4*)(aptr + aH2 * 4 + 8);
        }
        sA[0]=v0.x; sA[1]=v0.y; sA[2]=v0.z; sA[3]=v0.w;
        sA[4]=v1.x; sA[5]=v1.y; sA[6]=v1.z; sA[7]=v1.w;
    }
#pragma unroll
    for (int j = 0; j < 2; j++) {
        int q = 2 * bH + j;
        int k = 2 * q;
        float b0 = 0.f, b1 = 0.f, b2 = 0.f, b3 = 0.f;
        if (bok) {
            b0 = B[(size_t)k * N + gn];
            b1 = B[(size_t)(k + 1) * N + gn];
            b2 = B[(size_t)(k + 8) * N + gn];
            b3 = B[(size_t)(k + 9) * N + gn];
        }
        sB[j*4+0]=b0; sB[j*4+1]=b1; sB[j*4+2]=b2; sB[j*4+3]=b3;
    }
    if (aprod) {
#pragma unroll
        for (int j = 0; j < 2; j++) {
            uint4 p;
            bf16split2(sA[j*2+0], sA[j*2+1], p.x, p.z);
            bf16split2(sA[j*2+4], sA[j*2+5], p.y, p.w);
            AP[aRow * 5 + 2 * aH2 + j] = p;
        }
    }
#pragma unroll
    for (int j = 0; j < 2; j++) {
        uint4 p;
        bf16split2(sB[j*4+0], sB[j*4+1], p.x, p.z);
        bf16split2(sB[j*4+2], sB[j*4+3], p.y, p.w);
        BP[bN * 5 + 2 * bH + j] = p;
    }
    __syncthreads();

    int buf = 0;
    for (int k0 = 0; k0 < K; k0 += 16) {
        bool has_next = (k0 + 16 < K);
        if (has_next) {
            if (aprod) {
                float4 v0 = make_float4(0.f,0.f,0.f,0.f), v1 = v0;
                if (aok) {
                    v0 = *(const float4*)(aptr + k0 + 16 + aH2 * 4);
                    v1 = *(const float4*)(aptr + k0 + 16 + aH2 * 4 + 8);
                }
                sA[0]=v0.x; sA[1]=v0.y; sA[2]=v0.z; sA[3]=v0.w;
                sA[4]=v1.x; sA[5]=v1.y; sA[6]=v1.z; sA[7]=v1.w;
            }
#pragma unroll
            for (int j = 0; j < 2; j++) {
                int q = 2 * bH + j;
                int k = k0 + 16 + 2 * q;
                float b0 = 0.f, b1 = 0.f, b2 = 0.f, b3 = 0.f;
                if (bok) {
                    b0 = B[(size_t)k * N + gn];
                    b1 = B[(size_t)(k + 1) * N + gn];
                    b2 = B[(size_t)(k + 8) * N + gn];
                    b3 = B[(size_t)(k + 9) * N + gn];
                }
                sB[j*4+0]=b0; sB[j*4+1]=b1; sB[j*4+2]=b2; sB[j*4+3]=b3;
            }
        }

        const uint4* APc = AP + buf * BA_STG;
        const uint4* BPc = BP + buf * BB_STG;
        int ra = lane >> 2;
        int q  = lane & 3;
        uint32_t aHf[2][4], aLf[2][4];
#pragma unroll
        for (int fm = 0; fm < 2; fm++) {
            int m = wm + fm * 16 + ra;
            uint4 f0 = APc[m * 5 + q];
            uint4 f1 = APc[(m + 8) * 5 + q];
            aHf[fm][0] = f0.x; aHf[fm][1] = f1.x;
            aHf[fm][2] = f0.y; aHf[fm][3] = f1.y;
            aLf[fm][0] = f0.z; aLf[fm][1] = f1.z;
            aLf[fm][2] = f0.w; aLf[fm][3] = f1.w;
        }
        uint4 fb = BPc[(wn + ra) * 5 + q];
#pragma unroll
        for (int fn = 0; fn < 4; fn++) {
            uint4 fbn = fb;
            if (fn < 3) fbn = BPc[(wn + (fn + 1) * 8 + ra) * 5 + q];
#pragma unroll
            for (int fm = 0; fm < 2; fm++) {
                mma_bf16(c[fm][fn], aLf[fm][0], aLf[fm][1], aLf[fm][2], aLf[fm][3], fb.x, fb.y);
                mma_bf16(c[fm][fn], aHf[fm][0], aHf[fm][1], aHf[fm][2], aHf[fm][3], fb.z, fb.w);
                mma_bf16(c[fm][fn], aHf[fm][0], aHf[fm][1], aHf[fm][2], aHf[fm][3], fb.x, fb.y);
            }
            fb = fbn;
        }

        if (has_next) {
            uint4* APn = AP + (buf ^ 1) * BA_STG;
            uint4* BPn = BP + (buf ^ 1) * BB_STG;
            if (aprod) {
#pragma unroll
                for (int j = 0; j < 2; j++) {
                    uint4 p;
                    bf16split2(sA[j*2+0], sA[j*2+1], p.x, p.z);
                    bf16split2(sA[j*2+4], sA[j*2+5], p.y, p.w);
                    APn[aRow * 5 + 2 * aH2 + j] = p;
                }
            }
#pragma unroll
            for (int j = 0; j < 2; j++) {
                uint4 p;
                bf16split2(sB[j*4+0], sB[j*4+1], p.x, p.z);
                bf16split2(sB[j*4+2], sB[j*4+3], p.y, p.w);
                BPn[bN * 5 + 2 * bH + j] = p;
            }
        }
        __syncthreads();
        buf ^= 1;
    }

#pragma unroll
    for (int fm = 0; fm < 2; fm++) {
#pragma unroll
        for (int half = 0; half < 2; half++) {
            int mrel = m0 + wm + fm * 16 + (lane >> 2) + half * 8;
            if (mrel >= M) continue;
            size_t crow = (size_t)mrel * (size_t)ldc;
#pragma unroll
            for (int fn = 0; fn < 4; fn++) {
                int n = n0 + wn + fn * 8 + (lane & 3) * 2;
                if (n < N)     C[crow + n]     = c[fm][fn][half * 2 + 0] + bias[n];
                if (n + 1 < N) C[crow + n + 1] = c[fm][fn][half * 2 + 1] + bias[n + 1];
            }
        }
    }
}

// ---------------- flash-style GQA attention (fp32, reads combined QKV) ----------------
__global__ __launch_bounds__(256) void attn_kernel(
    const float* __restrict__ qkv, const int* __restrict__ amask,
    float* __restrict__ ao)
{
    const float SCALE = 0.125f;
    int head = blockIdx.y;
    int g    = head / (NHD / NG);
    int q0   = blockIdx.x * 64;

    __shared__ float QsT[64][68];
    __shared__ float KsT[64][33];
    __shared__ float Vs [32][68];
    __shared__ float PsT[32][68];
    __shared__ float Mk [32];

    int tid = threadIdx.x;
#pragma unroll
    for (int i = 0; i < 4; i++) {
        int idx = tid + i * 256;
        int r = idx >> 4;
        int dseg = (idx & 15) * 4;
        float4 qv = *(const float4*)(qkv + (size_t)(q0 + r) * QKVN + head * 64 + dseg);
        QsT[dseg + 0][r] = qv.x; QsT[dseg + 1][r] = qv.y;
        QsT[dseg + 2][r] = qv.z; QsT[dseg + 3][r] = qv.w;
    }

    int rg = tid >> 4, kg = tid & 15;
    int r0 = rg * 4, d0 = kg * 4, j0 = kg * 2;

    float acc[4][4] = {};
    float m[4], l[4];
#pragma unroll
    for (int i = 0; i < 4; i++) { m[i] = -3.0e38f; l[i] = 0.f; }

    for (int kc = 0; kc < 32; kc++) {
        int kbase = kc * 32;
#pragma unroll
        for (int i = 0; i < 2; i++) {
            int idx = tid + i * 256;
            int kk = idx >> 4;
            int dseg = (idx & 15) * 4;
            float4 kv = *(const float4*)(qkv + (size_t)(kbase + kk) * QKVN + HID + g * 64 + dseg);
            KsT[dseg + 0][kk] = kv.x; KsT[dseg + 1][kk] = kv.y;
            KsT[dseg + 2][kk] = kv.z; KsT[dseg + 3][kk] = kv.w;
            float4 vv = *(const float4*)(qkv + (size_t)(kbase + kk) * QKVN + HID + 256 + g * 64 + dseg);
            *(float4*)&Vs[kk][dseg] = vv;
        }
        if (tid < 32) Mk[tid] = (amask[kbase + tid] == 0) ? -3.0e38f : 0.f;
        __syncthreads();

        float s0[4] = {}, s1[4] = {};
#pragma unroll
        for (int d = 0; d < 64; d++) {
            float4 a = *(const float4*)&QsT[d][r0];
            float b0 = KsT[d][j0], b1 = KsT[d][j0 + 1];
            s0[0] += a.x * b0; s1[0] += a.x * b1;
            s0[1] += a.y * b0; s1[1] += a.y * b1;
            s0[2] += a.z * b0; s1[2] += a.z * b1;
            s0[3] += a.w * b0; s1[3] += a.w * b1;
        }
        float mk0 = Mk[j0], mk1 = Mk[j0 + 1];
        float cm[4];
#pragma unroll
        for (int i = 0; i < 4; i++) {
            s0[i] = s0[i] * SCALE + mk0;
            s1[i] = s1[i] * SCALE + mk1;
            cm[i] = fmaxf(s0[i], s1[i]);
        }
#pragma unroll
        for (int o = 1; o < 16; o <<= 1)
#pragma unroll
            for (int i = 0; i < 4; i++)
                cm[i] = fmaxf(cm[i], __shfl_xor_sync(0xffffffffu, cm[i], o));

        float p0[4], p1[4], csum[4];
#pragma unroll
        for (int i = 0; i < 4; i++) {
            float nm = fmaxf(m[i], cm[i]);
            float alpha = expf(m[i] - nm);
            m[i] = nm;
            p0[i] = expf(s0[i] - nm);
            p1[i] = expf(s1[i] - nm);
            csum[i] = p0[i] + p1[i];
            l[i] *= alpha;
#pragma unroll
            for (int j = 0; j < 4; j++) acc[i][j] *= alpha;
        }
#pragma unroll
        for (int o = 1; o < 16; o <<= 1)
#pragma unroll
            for (int i = 0; i < 4; i++)
                csum[i] += __shfl_xor_sync(0xffffffffu, csum[i], o);
#pragma unroll
        for (int i = 0; i < 4; i++) l[i] += csum[i];

#pragma unroll
        for (int i = 0; i < 4; i++) {
            PsT[j0][r0 + i]     = p0[i];
            PsT[j0 + 1][r0 + i] = p1[i];
        }
        __syncthreads();

#pragma unroll
        for (int key = 0; key < 32; key++) {
            float4 pv = *(const float4*)&PsT[key][r0];
            float4 vv = *(const float4*)&Vs[key][d0];
            acc[0][0] += pv.x * vv.x; acc[0][1] += pv.x * vv.y; acc[0][2] += pv.x * vv.z; acc[0][3] += pv.x * vv.w;
            acc[1][0] += pv.y * vv.x; acc[1][1] += pv.y * vv.y; acc[1][2] += pv.y * vv.z; acc[1][3] += pv.y * vv.w;
            acc[2][0] += pv.z * vv.x; acc[2][1] += pv.z * vv.y; acc[2][2] += pv.z * vv.z; acc[2][3] += pv.z * vv.w;
            acc[3][0] += pv.w * vv.x; acc[3][1] += pv.w * vv.y; acc[3][2] += pv.w * vv.z; acc[3][3] += pv.w * vv.w;
        }
        __syncthreads();
    }

#pragma unroll
    for (int i = 0; i < 4; i++) {
        float inv = 1.f / l[i];
        float4 o;
        o.x = acc[i][0] * inv; o.y = acc[i][1] * inv;
        o.z = acc[i][2] * inv; o.w = acc[i][3] * inv;
        *(float4*)(ao + (size_t)(q0 + r0 + i) * HID + head * 64 + d0) = o;
    }
}

// ---------------- layernorm: h = LN(h + res); optionally zero cnt ---------
__global__ __launch_bounds__(256) void ln_kernel(float* __restrict__ h,
                                                 const float* __restrict__ res,
                                                 const float* __restrict__ gam,
                                                 const float* __restrict__ bet,
                                                 int* __restrict__ czero) {
    int row = blockIdx.x;
    __shared__ float xbuf[HID];
    __shared__ float red[256];
    int tid = threadIdx.x;
    if (czero && row == 0 && tid < NEXP) czero[tid] = 0;
    float lsum = 0.f;
    for (int c = tid; c < HID; c += 256) {
        float v = h[(size_t)row * HID + c] + res[(size_t)row * HID + c];
        xbuf[c] = v;
        lsum += v;
    }
    red[tid] = lsum; __syncthreads();
    for (int s = 128; s > 0; s >>= 1) { if (tid < s) red[tid] += red[tid + s]; __syncthreads(); }
    float mean = red[0] / (float)HID;
    __syncthreads();
    float lvar = 0.f;
    for (int c = tid; c < HID; c += 256) { float d = xbuf[c] - mean; lvar += d * d; }
    red[tid] = lvar; __syncthreads();
    for (int s = 128; s > 0; s >>= 1) { if (tid < s) red[tid] += red[tid + s]; __syncthreads(); }
    float rstd = rsqrtf(red[0] / (float)HID + 1e-5f);
    for (int c = tid; c < HID; c += 256)
        h[(size_t)row * HID + c] = (xbuf[c] - mean) * rstd * gam[c] + bet[c];
}

// ---------------- fused MoE combine + layernorm: h = LN(h + combine) ------
__global__ __launch_bounds__(256) void combine_ln_kernel(
    float* __restrict__ h, const float* __restrict__ eo,
    const float* __restrict__ gates, const int* __restrict__ tslot,
    const float* __restrict__ gam, const float* __restrict__ bet)
{
    int row = blockIdx.x;
    int s0 = tslot[row * 2], s1 = tslot[row * 2 + 1];
    float g0 = gates[row * 2], g1 = gates[row * 2 + 1];
    __shared__ float xbuf[HID];
    __shared__ float red[256];
    int tid = threadIdx.x;
    float lsum = 0.f;
    for (int c = tid; c < HID; c += 256) {
        float r = g0 * eo[(size_t)s0 * HID + c] + g1 * eo[(size_t)s1 * HID + c];
        float v = h[(size_t)row * HID + c] + r;
        xbuf[c] = v;
        lsum += v;
    }
    red[tid] = lsum; __syncthreads();
    for (int s = 128; s > 0; s >>= 1) { if (tid < s) red[tid] += red[tid + s]; __syncthreads(); }
    float mean = red[0] / (float)HID;
    __syncthreads();
    float lvar = 0.f;
    for (int c = tid; c < HID; c += 256) { float d = xbuf[c] - mean; lvar += d * d; }
    red[tid] = lvar; __syncthreads();
    for (int s = 128; s > 0; s >>= 1) { if (tid < s) red[tid] += red[tid + s]; __syncthreads(); }
    float rstd = rsqrtf(red[0] / (float)HID + 1e-5f);
    for (int c = tid; c < HID; c += 256)
        h[(size_t)row * HID + c] = (xbuf[c] - mean) * rstd * gam[c] + bet[c];
}

// ---------------- router: top-2 gating ----------------
__global__ __launch_bounds__(256) void router_kernel(
    const float* __restrict__ h, const float* __restrict__ rw,
    const float* __restrict__ rb, float* __restrict__ gates,
    int* __restrict__ texp, int* __restrict__ tlocal, int* __restrict__ cnt)
{
    int t = blockIdx.x;
    int tid = threadIdx.x;
    int e = tid >> 5, lane = tid & 31;
    float sum = 0.f;
    for (int i = lane; i < HID; i += 32)
        sum += h[(size_t)t * HID + i] * rw[i * NEXP + e];
#pragma unroll
    for (int o = 16; o > 0; o >>= 1) sum += __shfl_down_sync(0xffffffffu, sum, o);
    __shared__ float logits[NEXP];
    if (lane == 0) logits[e] = sum + rb[e];
    __syncthreads();
    if (tid == 0) {
        float mx = logits[0];
        for (int i = 1; i < NEXP; i++) mx = fmaxf(mx, logits[i]);
        float ex[NEXP], ssum = 0.f;
        for (int i = 0; i < NEXP; i++) { ex[i] = expf(logits[i] - mx); ssum += ex[i]; }
        float p[NEXP];
        for (int i = 0; i < NEXP; i++) p[i] = ex[i] / ssum;
        int i0 = 0;
        for (int i = 1; i < NEXP; i++) if (p[i] > p[i0]) i0 = i;
        int i1 = (i0 == 0) ? 1 : 0;
        for (int i = 0; i < NEXP; i++) if (i != i0 && p[i] > p[i1]) i1 = i;
        float b = expf(p[i1] - p[i0]);
        float g0 = 1.f / (1.f + b);
        float g1 = b / (1.f + b);
        gates[t * 2] = g0; gates[t * 2 + 1] = g1;
        texp[t * 2] = i0; texp[t * 2 + 1] = i1;
        tlocal[t * 2]     = atomicAdd(&cnt[i0], 1);
        tlocal[t * 2 + 1] = atomicAdd(&cnt[i1], 1);
    }
}

__global__ __launch_bounds__(256) void assign_kernel(
    const int* __restrict__ cnt, int* __restrict__ offs, int* __restrict__ perm,
    const int* __restrict__ texp, const int* __restrict__ tlocal,
    int* __restrict__ tslot, int* __restrict__ loads)
{
    __shared__ int so[NEXP];
    if (threadIdx.x == 0) {
        int acc = 0;
        for (int e = 0; e < NEXP; e++) {
            so[e] = acc; offs[e] = acc; loads[e] = cnt[e]; acc += cnt[e];
        }
    }
    __syncthreads();
    for (int i = threadIdx.x; i < 2 * SQ; i += blockDim.x) {
        int t = i >> 1;
        int slot = so[texp[i]] + tlocal[i];
        perm[slot] = t;
        tslot[i] = slot;
    }
}

__global__ void loss_kernel(const int* __restrict__ loads, float* __restrict__ out) {
    int l = threadIdx.x;
    if (l < NLAY) {
        float mean = (float)(2 * SQ) / (float)NEXP;
        float var = 0.f;
        for (int e = 0; e < NEXP; e++) {
            float d = (float)loads[l * NEXP + e] - mean;
            var += d * d;
        }
        var /= (float)(NEXP - 1);
        out[l] = var / (mean * mean);
    }
}

// ---------------- host launch ----------------
static void launch_gemm(const float* A, const float* B, const float* bias,
                        float* C, int M, int N, int K, int lda, int ldc) {
    dim3 grid((N + 127) / 128, (M + 63) / 64);
    mma_gemm<false, false, false><<<grid, 256, GEMM_SMEM>>>(
        A, B, bias, C, M, N, K, lda, ldc, nullptr, nullptr, nullptr, 0, 0);
}

extern "C" void kernel_launch(void* const* d_in, const int* in_sizes, int n_in,
                              void* d_out, int out_size) {
    const int*   ids   = (const int*)d_in[0];
    const int*   amask = (const int*)d_in[1];
    const float* emb   = (const float*)d_in[2];
    const float* pos   = (const float*)d_in[3];
    const float* qw    = (const float*)d_in[4];
    const float* qb    = (const float*)d_in[5];
    const float* kw    = (const float*)d_in[6];
    const float* kb    = (const float*)d_in[7];
    const float* vw    = (const float*)d_in[8];
    const float* vb    = (const float*)d_in[9];
    const float* rw    = (const float*)d_in[10];
    const float* rb    = (const float*)d_in[11];
    const float* fc1w  = (const float*)d_in[12];
    const float* fc1b  = (const float*)d_in[13];
    const float* fc2w  = (const float*)d_in[14];
    const float* fc2b  = (const float*)d_in[15];
    const float* lng   = (const float*)d_in[16];
    const float* lnb   = (const float*)d_in[17];
    const float* ow    = (const float*)d_in[18];
    const float* ob    = (const float*)d_in[19];
    float* out = (float*)d_out;

    cudaFuncSetAttribute(mma_gemm<false, false, false>,
                         cudaFuncAttributeMaxDynamicSharedMemorySize, GEMM_SMEM);
    cudaFuncSetAttribute(mma_gemm<true, true, true>,
                         cudaFuncAttributeMaxDynamicSharedMemorySize, GEMM_SMEM);
    cudaFuncSetAttribute(mma_gemm<false, true, false>,
                         cudaFuncAttributeMaxDynamicSharedMemorySize, GEMM_SMEM);
    cudaFuncSetAttribute(mma_gemm_bf16,
                         cudaFuncAttributeMaxDynamicSharedMemorySize, GEMM_SMEM_BF);

    float *h, *res, *qkv, *wqkv, *bqkv, *h1, *eo, *gates;
    int *texp, *tlocal, *tslot, *cnt, *offs, *perm, *loads;
    cudaGetSymbolAddress((void**)&h, g_h);
    cudaGetSymbolAddress((void**)&res, g_res);
    cudaGetSymbolAddress((void**)&qkv, g_qkv);
    cudaGetSymbolAddress((void**)&wqkv, g_wqkv);
    cudaGetSymbolAddress((void**)&bqkv, g_bqkv);
    cudaGetSymbolAddress((void**)&h1, g_h1);
    cudaGetSymbolAddress((void**)&eo, g_eo);
    cudaGetSymbolAddress((void**)&gates, g_gates);
    cudaGetSymbolAddress((void**)&texp, g_texp);
    cudaGetSymbolAddress((void**)&tlocal, g_tlocal);
    cudaGetSymbolAddress((void**)&tslot, g_tslot);
    cudaGetSymbolAddress((void**)&cnt, g_cnt);
    cudaGetSymbolAddress((void**)&offs, g_offs);
    cudaGetSymbolAddress((void**)&perm, g_perm);
    cudaGetSymbolAddress((void**)&loads, g_loads);

    {
        size_t tot = (size_t)NLAY * HID * QKVN;
        pack_qkv_w<<<(unsigned)((tot + 255) / 256), 256>>>(qw, kw, vw, wqkv);
        pack_qkv_b<<<(NLAY * QKVN + 255) / 256, 256>>>(qb, kb, vb, bqkv);
    }

    embed_kernel<<<SQ, 256>>>(ids, emb, pos, h);

    for (int l = 0; l < NLAY; l++) {
        const float* rw_l = rw + (size_t)l * HID * NEXP;
        const float* rb_l = rb + (size_t)l * NEXP;
        const float* fc1w_l = fc1w + (size_t)l * NEXP * HID * FFD;
        const float* fc1b_l = fc1b + (size_t)l * NEXP * FFD;
        const float* fc2w_l = fc2w + (size_t)l * NEXP * FFD * HID;
        const float* fc2b_l = fc2b + (size_t)l * NEXP * HID;

        // fused QKV projection: [1024,768] @ [768,1280]
        launch_gemm(h, wqkv + (size_t)l * HID * QKVN, bqkv + (size_t)l * QKVN,
                    qkv, SQ, QKVN, HID, HID, QKVN);

        attn_kernel<<<dim3(SQ / 64, NHD), 256>>>(qkv, amask, res);
        // LN also zeroes the expert counters for the router below
        ln_kernel<<<SQ, 256>>>(h, res, lng, lnb, cnt);

        router_kernel<<<SQ, 256>>>(h, rw_l, rb_l, gates, texp, tlocal, cnt);
        assign_kernel<<<1, 256>>>(cnt, offs, perm, texp, tlocal, tslot, loads + l * NEXP);

        {   // fc1 + gelu (gathered rows)
            dim3 grid(FFD / 128, SQ / 64, NEXP);
            mma_gemm<true, true, true><<<grid, 256, GEMM_SMEM>>>(
                h, fc1w_l, fc1b_l, h1, SQ, FFD, HID, HID, FFD,
                perm, offs, cnt, (size_t)HID * FFD, (size_t)FFD);
        }
        {   // fc2 (contiguous slots)
            dim3 grid(HID / 128, SQ / 64, NEXP);
            mma_gemm<false, true, false><<<grid, 256, GEMM_SMEM>>>(
                h1, fc2w_l, fc2b_l, eo, SQ, HID, FFD, FFD, HID,
                nullptr, offs, cnt, (size_t)FFD * HID, (size_t)HID);
        }
        combine_ln_kernel<<<SQ, 256>>>(h, eo, gates, tslot, lng, lnb);
    }

    // final logits projection with 2xBF16 split; M-tiles fastest for L2 B reuse
    {
        dim3 grid(SQ / 64, (NVOC + 127) / 128);
        mma_gemm_bf16<<<grid, 256, GEMM_SMEM_BF>>>(
            h, ow, ob, out, SQ, NVOC, HID, HID, NVOC);
    }
    loss_kernel<<<1, 32>>>(loads, out + ((size_t)out_size - NLAY));
}

// round 16
// speedup vs baseline: 1.1961x; 1.0375x over previous
#include <cuda_runtime.h>
#include <math.h>
#include <stdint.h>

#define SQ   1024
#define HID  768
#define NHD  12
#define DH   64
#define NG   4
#define NLAY 4
#define NEXP 8
#define FFD  3072
#define NVOC 50257
#define QKVN 1280   // 768 + 256 + 256

// ---------------- scratch (device globals; no allocation) ----------------
__device__ float g_h[SQ * HID];
__device__ float g_res[SQ * HID];
__device__ float g_qkv[SQ * QKVN];
__device__ float g_part[2 * SQ * QKVN];
__device__ float g_wqkv[NLAY * HID * QKVN];
__device__ float g_bqkv[NLAY * QKVN];
__device__ float g_h1[2 * SQ * FFD];
__device__ float g_eo[2 * SQ * HID];
__device__ float g_gates[SQ * 2];
__device__ int   g_texp[SQ * 2];
__device__ int   g_tlocal[SQ * 2];
__device__ int   g_tslot[SQ * 2];
__device__ int   g_cnt[NEXP];
__device__ int   g_offs[NEXP];
__device__ int   g_perm[2 * SQ];
__device__ int   g_loads[NLAY * NEXP];

// ---------------- embedding ----------------
__global__ void embed_kernel(const int* __restrict__ ids,
                             const float* __restrict__ emb,
                             const float* __restrict__ pos,
                             float* __restrict__ h) {
    int s = blockIdx.x;
    int id = ids[s];
    for (int c = threadIdx.x; c < HID; c += blockDim.x)
        h[(size_t)s * HID + c] = emb[(size_t)id * HID + c] + pos[(size_t)s * HID + c];
}

// ---------------- pack qw|kw|vw -> wqkv ----------------
__global__ __launch_bounds__(256) void pack_qkv_w(
    const float* __restrict__ qw, const float* __restrict__ kw,
    const float* __restrict__ vw, float* __restrict__ wqkv)
{
    size_t idx = (size_t)blockIdx.x * 256 + threadIdx.x;
    if (idx >= (size_t)NLAY * HID * QKVN) return;
    int j = (int)(idx % QKVN);
    size_t li = idx / QKVN;
    float v;
    if (j < HID)            v = qw[li * HID + j];
    else if (j < HID + 256) v = kw[li * 256 + (j - HID)];
    else                    v = vw[li * 256 + (j - HID - 256)];
    wqkv[idx] = v;
}

__global__ void pack_qkv_b(const float* __restrict__ qb, const float* __restrict__ kb,
                           const float* __restrict__ vb, float* __restrict__ bqkv)
{
    int idx = blockIdx.x * 256 + threadIdx.x;
    if (idx >= NLAY * QKVN) return;
    int l = idx / QKVN, j = idx % QKVN;
    float v;
    if (j < HID)            v = qb[l * HID + j];
    else if (j < HID + 256) v = kb[l * 256 + (j - HID)];
    else                    v = vb[l * 256 + (j - HID - 256)];
    bqkv[idx] = v;
}

// qkv = part0 + part1 + bias
__global__ __launch_bounds__(256) void add_qkv_kernel(
    const float* __restrict__ part, const float* __restrict__ bias,
    float* __restrict__ qkv)
{
    int i = blockIdx.x * 256 + threadIdx.x;
    qkv[i] = part[i] + part[SQ * QKVN + i] + bias[i % QKVN];
}

// ---------------- tf32 helpers ----------------
__device__ __forceinline__ uint32_t f2tf(float x) {
    uint32_t r;
    asm("cvt.rna.tf32.f32 %0, %1;" : "=r"(r) : "f"(x));
    return r;
}

__device__ __forceinline__ void mma_tf32(float c[4],
                                         uint32_t a0, uint32_t a1, uint32_t a2, uint32_t a3,
                                         uint32_t b0, uint32_t b1) {
    asm volatile(
        "mma.sync.aligned.m16n8k8.row.col.f32.tf32.tf32.f32 "
        "{%0,%1,%2,%3}, {%4,%5,%6,%7}, {%8,%9}, {%0,%1,%2,%3};"
        : "+f"(c[0]), "+f"(c[1]), "+f"(c[2]), "+f"(c[3])
        : "r"(a0), "r"(a1), "r"(a2), "r"(a3), "r"(b0), "r"(b1));
}

__device__ __forceinline__ uint4 tf_pack(float v0, float v4) {
    uint4 p;
    p.x = f2tf(v0);
    p.y = f2tf(v4);
    p.z = f2tf(v0 - __uint_as_float(p.x));
    p.w = f2tf(v4 - __uint_as_float(p.y));
    return p;
}

// ---------------- bf16 helpers ----------------
__device__ __forceinline__ uint32_t bf16pack2(float x0, float x1) {
    uint32_t r;
    asm("cvt.rn.bf16x2.f32 %0, %1, %2;" : "=r"(r) : "f"(x1), "f"(x0));
    return r;
}
__device__ __forceinline__ void bf16split2(float x0, float x1, uint32_t& hi, uint32_t& lo) {
    hi = bf16pack2(x0, x1);
    float h0 = __uint_as_float(hi << 16);
    float h1 = __uint_as_float(hi & 0xFFFF0000u);
    lo = bf16pack2(x0 - h0, x1 - h1);
}

__device__ __forceinline__ void mma_bf16(float c[4],
                                         uint32_t a0, uint32_t a1, uint32_t a2, uint32_t a3,
                                         uint32_t b0, uint32_t b1) {
    asm volatile(
        "mma.sync.aligned.m16n8k16.row.col.f32.bf16.bf16.f32 "
        "{%0,%1,%2,%3}, {%4,%5,%6,%7}, {%8,%9}, {%0,%1,%2,%3};"
        : "+f"(c[0]), "+f"(c[1]), "+f"(c[2]), "+f"(c[3])
        : "r"(a0), "r"(a1), "r"(a2), "r"(a3), "r"(b0), "r"(b1));
}

#define ASTG 576            // 64 rows * 9 uint4
#define BSTG 1152           // 128 rows * 9 uint4
#define GEMM_SMEM (2 * (ASTG + BSTG) * 16)   // 55296 bytes

// ---------------- 3xTF32 GEMM: 64(M)x128(N) tile, double-buffered ----------
// SPLITK: blockIdx.z in {0,1} takes K/2; writes raw partial (no bias) to
// C + z*M*ldc.
template<bool GELU, bool EXPERT, bool GATHER, bool SPLITK>
__global__ __launch_bounds__(256, 2) void mma_gemm(
    const float* __restrict__ A, const float* __restrict__ B,
    const float* __restrict__ bias, float* __restrict__ C,
    int M, int N, int K, int lda, int ldc,
    const int* __restrict__ perm, const int* __restrict__ offs,
    const int* __restrict__ cnts, size_t strideB, size_t strideBias)
{
    extern __shared__ uint4 sm4[];
    uint4* AP = sm4;
    uint4* BP = sm4 + 2 * ASTG;

    int mcount = M, base = 0;
    if (EXPERT) {
        int e = blockIdx.z;
        mcount = cnts[e];
        base   = offs[e];
        B     += (size_t)e * strideB;
        bias  += (size_t)e * strideBias;
    }
    if (SPLITK) {
        int z = blockIdx.z;
        int kb = (K >> 1) * z;
        A += kb;
        B += (size_t)kb * (size_t)N;
        C += (size_t)z * (size_t)M * (size_t)ldc;
        K >>= 1;
    }
    int m0 = blockIdx.y * 64;
    if (m0 >= mcount) return;
    int n0 = blockIdx.x * 128;

    int tid = threadIdx.x, lane = tid & 31, warp = tid >> 5;
    int wm = (warp & 1) * 32;
    int wn = (warp >> 1) * 32;

    int aRow = tid >> 1;
    int aKK  = tid & 1;
    bool aprod = (tid < 128);
    bool aok = aprod && (m0 + aRow < mcount);
    const float* aptr = A;
    if (aok) {
        int phys = GATHER ? perm[base + m0 + aRow]
                          : (EXPERT ? base + m0 + aRow : m0 + aRow);
        aptr = A + (size_t)phys * (size_t)lda;
    }
    int bN   = tid & 127;
    int bKQ0 = tid >> 7;
    int gn   = n0 + bN;
    bool bok = (gn < N);

    float c[2][4][4];
#pragma unroll
    for (int i = 0; i < 2; i++)
#pragma unroll
        for (int j = 0; j < 4; j++)
#pragma unroll
            for (int q = 0; q < 4; q++) c[i][j][q] = 0.f;

    float stA[8], stB[8];

    if (aprod) {
        float4 v0 = make_float4(0.f,0.f,0.f,0.f), v1 = v0;
        if (aok) {
            v0 = *(const float4*)(aptr + aKK * 8);
            v1 = *(const float4*)(aptr + aKK * 8 + 4);
        }
        stA[0]=v0.x; stA[1]=v0.y; stA[2]=v0.z; stA[3]=v0.w;
        stA[4]=v1.x; stA[5]=v1.y; stA[6]=v1.z; stA[7]=v1.w;
    }
#pragma unroll
    for (int j = 0; j < 4; j++) {
        int kq = bKQ0 + 2 * j;
        int krow = (kq >> 2) * 8 + (kq & 3);
        float b0 = 0.f, b1 = 0.f;
        if (bok) {
            b0 = B[(size_t)krow * (size_t)N + gn];
            b1 = B[(size_t)(krow + 4) * (size_t)N + gn];
        }
        stB[j * 2] = b0; stB[j * 2 + 1] = b1;
    }
    if (aprod) {
#pragma unroll
        for (int q = 0; q < 4; q++)
            AP[aRow * 9 + aKK * 4 + q] = tf_pack(stA[q], stA[q + 4]);
    }
#pragma unroll
    for (int j = 0; j < 4; j++) {
        int kq = bKQ0 + 2 * j;
        BP[bN * 9 + kq] = tf_pack(stB[j * 2], stB[j * 2 + 1]);
    }
    __syncthreads();

    int buf = 0;
    for (int k0 = 0; k0 < K; k0 += 16) {
        bool has_next = (k0 + 16 < K);
        if (has_next) {
            if (aprod) {
                float4 v0 = make_float4(0.f,0.f,0.f,0.f), v1 = v0;
                if (aok) {
                    v0 = *(const float4*)(aptr + k0 + 16 + aKK * 8);
                    v1 = *(const float4*)(aptr + k0 + 16 + aKK * 8 + 4);
                }
                stA[0]=v0.x; stA[1]=v0.y; stA[2]=v0.z; stA[3]=v0.w;
                stA[4]=v1.x; stA[5]=v1.y; stA[6]=v1.z; stA[7]=v1.w;
            }
#pragma unroll
            for (int j = 0; j < 4; j++) {
                int kq = bKQ0 + 2 * j;
                int krow = k0 + 16 + (kq >> 2) * 8 + (kq & 3);
                float b0 = 0.f, b1 = 0.f;
                if (bok) {
                    b0 = B[(size_t)krow * (size_t)N + gn];
                    b1 = B[(size_t)(krow + 4) * (size_t)N + gn];
                }
                stB[j * 2] = b0; stB[j * 2 + 1] = b1;
            }
        }

        const uint4* APc = AP + buf * ASTG;
        const uint4* BPc = BP + buf * BSTG;
        int ra = lane >> 2;
        int q  = lane & 3;
#pragma unroll
        for (int kk = 0; kk < 2; kk++) {
            int kkq = kk * 4 + q;
            uint32_t aH[2][4], aL[2][4];
#pragma unroll
            for (int fm = 0; fm < 2; fm++) {
                int m = wm + fm * 16 + ra;
                uint4 f0 = APc[m * 9 + kkq];
                uint4 f1 = APc[(m + 8) * 9 + kkq];
                aH[fm][0] = f0.x; aH[fm][1] = f1.x;
                aH[fm][2] = f0.y; aH[fm][3] = f1.y;
                aL[fm][0] = f0.z; aL[fm][1] = f1.z;
                aL[fm][2] = f0.w; aL[fm][3] = f1.w;
            }
#pragma unroll
            for (int fn = 0; fn < 4; fn++) {
                int n = wn + fn * 8 + ra;
                uint4 fb = BPc[n * 9 + kkq];
#pragma unroll
                for (int fm = 0; fm < 2; fm++) {
                    mma_tf32(c[fm][fn], aL[fm][0], aL[fm][1], aL[fm][2], aL[fm][3], fb.x, fb.y);
                    mma_tf32(c[fm][fn], aH[fm][0], aH[fm][1], aH[fm][2], aH[fm][3], fb.z, fb.w);
                    mma_tf32(c[fm][fn], aH[fm][0], aH[fm][1], aH[fm][2], aH[fm][3], fb.x, fb.y);
                }
            }
        }

        if (has_next) {
            uint4* APn = AP + (buf ^ 1) * ASTG;
            uint4* BPn = BP + (buf ^ 1) * BSTG;
            if (aprod) {
#pragma unroll
                for (int qq = 0; qq < 4; qq++)
                    APn[aRow * 9 + aKK * 4 + qq] = tf_pack(stA[qq], stA[qq + 4]);
            }
#pragma unroll
            for (int j = 0; j < 4; j++) {
                int kq = bKQ0 + 2 * j;
                BPn[bN * 9 + kq] = tf_pack(stB[j * 2], stB[j * 2 + 1]);
            }
        }
        __syncthreads();
        buf ^= 1;
    }

#pragma unroll
    for (int fm = 0; fm < 2; fm++) {
#pragma unroll
        for (int half = 0; half < 2; half++) {
            int mrel = m0 + wm + fm * 16 + (lane >> 2) + half * 8;
            if (mrel >= mcount) continue;
            size_t crow = (size_t)(EXPERT ? base + mrel : mrel) * (size_t)ldc;
#pragma unroll
            for (int fn = 0; fn < 4; fn++) {
                int n = n0 + wn + fn * 8 + (lane & 3) * 2;
                float v0 = c[fm][fn][half * 2 + 0];
                float v1 = c[fm][fn][half * 2 + 1];
                if (n < N) {
                    float o = SPLITK ? v0 : v0 + bias[n];
                    if (GELU) o = 0.5f * o * (1.f + erff(o * 0.70710678118654752f));
                    C[crow + n] = o;
                }
                if (n + 1 < N) {
                    float o = SPLITK ? v1 : v1 + bias[n + 1];
                    if (GELU) o = 0.5f * o * (1.f + erff(o * 0.70710678118654752f));
                    C[crow + n + 1] = o;
                }
            }
        }
    }
}

// ---------------- 2xBF16 GEMM (logits): 128 threads, warp tile 32x64 -------
#define BA_STG (64 * 5)
#define BB_STG (128 * 5)
#define GEMM_SMEM_BF (2 * (BA_STG + BB_STG) * 16)   // 30720 bytes

__global__ __launch_bounds__(128) void mma_gemm_bf16(
    const float* __restrict__ A, const float* __restrict__ B,
    const float* __restrict__ bias, float* __restrict__ C,
    int M, int N, int K, int lda, int ldc)
{
    extern __shared__ uint4 sm4[];
    uint4* AP = sm4;
    uint4* BP = sm4 + 2 * BA_STG;

    int m0 = blockIdx.x * 64;      // M fastest-varying for L2 B reuse
    int n0 = blockIdx.y * 128;

    int tid = threadIdx.x, lane = tid & 31, warp = tid >> 5;   // 4 warps
    int wm = (warp & 1) * 32;
    int wn = (warp >> 1) * 64;

    // A producer: row = tid>>1, aH2 = tid&1 (q pair)
    int aRow = tid >> 1;
    int aH2  = tid & 1;
    bool aok = (m0 + aRow < M);
    const float* aptr = A + (size_t)(m0 + aRow) * (size_t)lda;

    // B producer: col = tid, all 4 q groups
    int bN = tid;
    int gn = n0 + bN;
    bool bok = (gn < N);

    float c[2][8][4];
#pragma unroll
    for (int i = 0; i < 2; i++)
#pragma unroll
        for (int j = 0; j < 8; j++)
#pragma unroll
            for (int q = 0; q < 4; q++) c[i][j][q] = 0.f;

    float sA[8], sB[16];

    // ---- load tile 0 ----
    {
        float4 v0 = make_float4(0.f,0.f,0.f,0.f), v1 = v0;
        if (aok) {
            v0 = *(const float4*)(aptr + aH2 * 4);
            v1 = *(const float4*)(aptr + aH2 * 4 + 8);
        }
        sA[0]=v0.x; sA[1]=v0.y; sA[2]=v0.z; sA[3]=v0.w;
        sA[4]=v1.x; sA[5]=v1.y; sA[6]=v1.z; sA[7]=v1.w;
    }
#pragma unroll
    for (int q = 0; q < 4; q++) {
        int k = 2 * q;
        float b0=0.f, b1=0.f, b2=0.f, b3=0.f;
        if (bok) {
            b0 = B[(size_t)k * N + gn];
            b1 = B[(size_t)(k + 1) * N + gn];
            b2 = B[(size_t)(k + 8) * N + gn];
            b3 = B[(size_t)(k + 9) * N + gn];
        }
        sB[q*4+0]=b0; sB[q*4+1]=b1; sB[q*4+2]=b2; sB[q*4+3]=b3;
    }
    // ---- store stage 0 ----
#pragma unroll
    for (int j = 0; j < 2; j++) {
        uint4 p;
        bf16split2(sA[j*2+0], sA[j*2+1], p.x, p.z);
        bf16split2(sA[j*2+4], sA[j*2+5], p.y, p.w);
        AP[aRow * 5 + 2 * aH2 + j] = p;
    }
#pragma unroll
    for (int q = 0; q < 4; q++) {
        uint4 p;
        bf16split2(sB[q*4+0], sB[q*4+1], p.x, p.z);
        bf16split2(sB[q*4+2], sB[q*4+3], p.y, p.w);
        BP[bN * 5 + q] = p;
    }
    __syncthreads();

    int buf = 0;
    for (int k0 = 0; k0 < K; k0 += 16) {
        bool has_next = (k0 + 16 < K);
        if (has_next) {
            float4 v0 = make_float4(0.f,0.f,0.f,0.f), v1 = v0;
            if (aok) {
                v0 = *(const float4*)(aptr + k0 + 16 + aH2 * 4);
                v1 = *(const float4*)(aptr + k0 + 16 + aH2 * 4 + 8);
            }
            sA[0]=v0.x; sA[1]=v0.y; sA[2]=v0.z; sA[3]=v0.w;
            sA[4]=v1.x; sA[5]=v1.y; sA[6]=v1.z; sA[7]=v1.w;
#pragma unroll
            for (int q = 0; q < 4; q++) {
                int k = k0 + 16 + 2 * q;
                float b0=0.f, b1=0.f, b2=0.f, b3=0.f;
                if (bok) {
                    b0 = B[(size_t)k * N + gn];
                    b1 = B[(size_t)(k + 1) * N + gn];
                    b2 = B[(size_t)(k + 8) * N + gn];
                    b3 = B[(size_t)(k + 9) * N + gn];
                }
                sB[q*4+0]=b0; sB[q*4+1]=b1; sB[q*4+2]=b2; sB[q*4+3]=b3;
            }
        }

        const uint4* APc = AP + buf * BA_STG;
        const uint4* BPc = BP + buf * BB_STG;
        int ra = lane >> 2;
        int q  = lane & 3;
        uint32_t aHf[2][4], aLf[2][4];
#pragma unroll
        for (int fm = 0; fm < 2; fm++) {
            int m = wm + fm * 16 + ra;
            uint4 f0 = APc[m * 5 + q];
            uint4 f1 = APc[(m + 8) * 5 + q];
            aHf[fm][0] = f0.x; aHf[fm][1] = f1.x;
            aHf[fm][2] = f0.y; aHf[fm][3] = f1.y;
            aLf[fm][0] = f0.z; aLf[fm][1] = f1.z;
            aLf[fm][2] = f0.w; aLf[fm][3] = f1.w;
        }
#pragma unroll
        for (int fn = 0; fn < 8; fn++) {
            uint4 fb = BPc[(wn + fn * 8 + ra) * 5 + q];
#pragma unroll
            for (int fm = 0; fm < 2; fm++) {
                mma_bf16(c[fm][fn], aLf[fm][0], aLf[fm][1], aLf[fm][2], aLf[fm][3], fb.x, fb.y);
                mma_bf16(c[fm][fn], aHf[fm][0], aHf[fm][1], aHf[fm][2], aHf[fm][3], fb.z, fb.w);
                mma_bf16(c[fm][fn], aHf[fm][0], aHf[fm][1], aHf[fm][2], aHf[fm][3], fb.x, fb.y);
            }
        }

        if (has_next) {
            uint4* APn = AP + (buf ^ 1) * BA_STG;
            uint4* BPn = BP + (buf ^ 1) * BB_STG;
#pragma unroll
            for (int j = 0; j < 2; j++) {
                uint4 p;
                bf16split2(sA[j*2+0], sA[j*2+1], p.x, p.z);
                bf16split2(sA[j*2+4], sA[j*2+5], p.y, p.w);
                APn[aRow * 5 + 2 * aH2 + j] = p;
            }
#pragma unroll
            for (int q2 = 0; q2 < 4; q2++) {
                uint4 p;
                bf16split2(sB[q2*4+0], sB[q2*4+1], p.x, p.z);
                bf16split2(sB[q2*4+2], sB[q2*4+3], p.y, p.w);
                BPn[bN * 5 + q2] = p;
            }
        }
        __syncthreads();
        buf ^= 1;
    }

#pragma unroll
    for (int fm = 0; fm < 2; fm++) {
#pragma unroll
        for (int half = 0; half < 2; half++) {
            int mrel = m0 + wm + fm * 16 + (lane >> 2) + half * 8;
            if (mrel >= M) continue;
            size_t crow = (size_t)mrel * (size_t)ldc;
#pragma unroll
            for (int fn = 0; fn < 8; fn++) {
                int n = n0 + wn + fn * 8 + (lane & 3) * 2;
                if (n < N)     C[crow + n]     = c[fm][fn][half * 2 + 0] + bias[n];
                if (n + 1 < N) C[crow + n + 1] = c[fm][fn][half * 2 + 1] + bias[n + 1];
            }
        }
    }
}

// ---------------- flash-style GQA attention (fp32, reads combined QKV) ----------------
__global__ __launch_bounds__(256) void attn_kernel(
    const float* __restrict__ qkv, const int* __restrict__ amask,
    float* __restrict__ ao)
{
    const float SCALE = 0.125f;
    int head = blockIdx.y;
    int g    = head / (NHD / NG);
    int q0   = blockIdx.x * 64;

    __shared__ float QsT[64][68];
    __shared__ float KsT[64][33];
    __shared__ float Vs [32][68];
    __shared__ float PsT[32][68];
    __shared__ float Mk [32];

    int tid = threadIdx.x;
#pragma unroll
    for (int i = 0; i < 4; i++) {
        int idx = tid + i * 256;
        int r = idx >> 4;
        int dseg = (idx & 15) * 4;
        float4 qv = *(const float4*)(qkv + (size_t)(q0 + r) * QKVN + head * 64 + dseg);
        QsT[dseg + 0][r] = qv.x; QsT[dseg + 1][r] = qv.y;
        QsT[dseg + 2][r] = qv.z; QsT[dseg + 3][r] = qv.w;
    }

    int rg = tid >> 4, kg = tid & 15;
    int r0 = rg * 4, d0 = kg * 4, j0 = kg * 2;

    float acc[4][4] = {};
    float m[4], l[4];
#pragma unroll
    for (int i = 0; i < 4; i++) { m[i] = -3.0e38f; l[i] = 0.f; }

    for (int kc = 0; kc < 32; kc++) {
        int kbase = kc * 32;
#pragma unroll
        for (int i = 0; i < 2; i++) {
            int idx = tid + i * 256;
            int kk = idx >> 4;
            int dseg = (idx & 15) * 4;
            float4 kv = *(const float4*)(qkv + (size_t)(kbase + kk) * QKVN + HID + g * 64 + dseg);
            KsT[dseg + 0][kk] = kv.x; KsT[dseg + 1][kk] = kv.y;
            KsT[dseg + 2][kk] = kv.z; KsT[dseg + 3][kk] = kv.w;
            float4 vv = *(const float4*)(qkv + (size_t)(kbase + kk) * QKVN + HID + 256 + g * 64 + dseg);
            *(float4*)&Vs[kk][dseg] = vv;
        }
        if (tid < 32) Mk[tid] = (amask[kbase + tid] == 0) ? -3.0e38f : 0.f;
        __syncthreads();

        float s0[4] = {}, s1[4] = {};
#pragma unroll
        for (int d = 0; d < 64; d++) {
            float4 a = *(const float4*)&QsT[d][r0];
            float b0 = KsT[d][j0], b1 = KsT[d][j0 + 1];
            s0[0] += a.x * b0; s1[0] += a.x * b1;
            s0[1] += a.y * b0; s1[1] += a.y * b1;
            s0[2] += a.z * b0; s1[2] += a.z * b1;
            s0[3] += a.w * b0; s1[3] += a.w * b1;
        }
        float mk0 = Mk[j0], mk1 = Mk[j0 + 1];
        float cm[4];
#pragma unroll
        for (int i = 0; i < 4; i++) {
            s0[i] = s0[i] * SCALE + mk0;
            s1[i] = s1[i] * SCALE + mk1;
            cm[i] = fmaxf(s0[i], s1[i]);
        }
#pragma unroll
        for (int o = 1; o < 16; o <<= 1)
#pragma unroll
            for (int i = 0; i < 4; i++)
                cm[i] = fmaxf(cm[i], __shfl_xor_sync(0xffffffffu, cm[i], o));

        float p0[4], p1[4], csum[4];
#pragma unroll
        for (int i = 0; i < 4; i++) {
            float nm = fmaxf(m[i], cm[i]);
            float alpha = expf(m[i] - nm);
            m[i] = nm;
            p0[i] = expf(s0[i] - nm);
            p1[i] = expf(s1[i] - nm);
            csum[i] = p0[i] + p1[i];
            l[i] *= alpha;
#pragma unroll
            for (int j = 0; j < 4; j++) acc[i][j] *= alpha;
        }
#pragma unroll
        for (int o = 1; o < 16; o <<= 1)
#pragma unroll
            for (int i = 0; i < 4; i++)
                csum[i] += __shfl_xor_sync(0xffffffffu, csum[i], o);
#pragma unroll
        for (int i = 0; i < 4; i++) l[i] += csum[i];

#pragma unroll
        for (int i = 0; i < 4; i++) {
            PsT[j0][r0 + i]     = p0[i];
            PsT[j0 + 1][r0 + i] = p1[i];
        }
        __syncthreads();

#pragma unroll
        for (int key = 0; key < 32; key++) {
            float4 pv = *(const float4*)&PsT[key][r0];
            float4 vv = *(const float4*)&Vs[key][d0];
            acc[0][0] += pv.x * vv.x; acc[0][1] += pv.x * vv.y; acc[0][2] += pv.x * vv.z; acc[0][3] += pv.x * vv.w;
            acc[1][0] += pv.y * vv.x; acc[1][1] += pv.y * vv.y; acc[1][2] += pv.y * vv.z; acc[1][3] += pv.y * vv.w;
            acc[2][0] += pv.z * vv.x; acc[2][1] += pv.z * vv.y; acc[2][2] += pv.z * vv.z; acc[2][3] += pv.z * vv.w;
            acc[3][0] += pv.w * vv.x; acc[3][1] += pv.w * vv.y; acc[3][2] += pv.w * vv.z; acc[3][3] += pv.w * vv.w;
        }
        __syncthreads();
    }

#pragma unroll
    for (int i = 0; i < 4; i++) {
        float inv = 1.f / l[i];
        float4 o;
        o.x = acc[i][0] * inv; o.y = acc[i][1] * inv;
        o.z = acc[i][2] * inv; o.w = acc[i][3] * inv;
        *(float4*)(ao + (size_t)(q0 + r0 + i) * HID + head * 64 + d0) = o;
    }
}

// ---------------- layernorm: h = LN(h + res); optionally zero cnt ---------
__global__ __launch_bounds__(256) void ln_kernel(float* __restrict__ h,
                                                 const float* __restrict__ res,
                                                 const float* __restrict__ gam,
                                                 const float* __restrict__ bet,
                                                 int* __restrict__ czero) {
    int row = blockIdx.x;
    __shared__ float xbuf[HID];
    __shared__ float red[256];
    int tid = threadIdx.x;
    if (czero && row == 0 && tid < NEXP) czero[tid] = 0;
    float lsum = 0.f;
    for (int c = tid; c < HID; c += 256) {
        float v = h[(size_t)row * HID + c] + res[(size_t)row * HID + c];
        xbuf[c] = v;
        lsum += v;
    }
    red[tid] = lsum; __syncthreads();
    for (int s = 128; s > 0; s >>= 1) { if (tid < s) red[tid] += red[tid + s]; __syncthreads(); }
    float mean = red[0] / (float)HID;
    __syncthreads();
    float lvar = 0.f;
    for (int c = tid; c < HID; c += 256) { float d = xbuf[c] - mean; lvar += d * d; }
    red[tid] = lvar; __syncthreads();
    for (int s = 128; s > 0; s >>= 1) { if (tid < s) red[tid] += red[tid + s]; __syncthreads(); }
    float rstd = rsqrtf(red[0] / (float)HID + 1e-5f);
    for (int c = tid; c < HID; c += 256)
        h[(size_t)row * HID + c] = (xbuf[c] - mean) * rstd * gam[c] + bet[c];
}

// ---------------- fused MoE combine + layernorm ----------------
__global__ __launch_bounds__(256) void combine_ln_kernel(
    float* __restrict__ h, const float* __restrict__ eo,
    const float* __restrict__ gates, const int* __restrict__ tslot,
    const float* __restrict__ gam, const float* __restrict__ bet)
{
    int row = blockIdx.x;
    int s0 = tslot[row * 2], s1 = tslot[row * 2 + 1];
    float g0 = gates[row * 2], g1 = gates[row * 2 + 1];
    __shared__ float xbuf[HID];
    __shared__ float red[256];
    int tid = threadIdx.x;
    float lsum = 0.f;
    for (int c = tid; c < HID; c += 256) {
        float r = g0 * eo[(size_t)s0 * HID + c] + g1 * eo[(size_t)s1 * HID + c];
        float v = h[(size_t)row * HID + c] + r;
        xbuf[c] = v;
        lsum += v;
    }
    red[tid] = lsum; __syncthreads();
    for (int s = 128; s > 0; s >>= 1) { if (tid < s) red[tid] += red[tid + s]; __syncthreads(); }
    float mean = red[0] / (float)HID;
    __syncthreads();
    float lvar = 0.f;
    for (int c = tid; c < HID; c += 256) { float d = xbuf[c] - mean; lvar += d * d; }
    red[tid] = lvar; __syncthreads();
    for (int s = 128; s > 0; s >>= 1) { if (tid < s) red[tid] += red[tid + s]; __syncthreads(); }
    float rstd = rsqrtf(red[0] / (float)HID + 1e-5f);
    for (int c = tid; c < HID; c += 256)
        h[(size_t)row * HID + c] = (xbuf[c] - mean) * rstd * gam[c] + bet[c];
}

// ---------------- router: top-2 gating ----------------
__global__ __launch_bounds__(256) void router_kernel(
    const float* __restrict__ h, const float* __restrict__ rw,
    const float* __restrict__ rb, float* __restrict__ gates,
    int* __restrict__ texp, int* __restrict__ tlocal, int* __restrict__ cnt)
{
    int t = blockIdx.x;
    int tid = threadIdx.x;
    int e = tid >> 5, lane = tid & 31;
    float sum = 0.f;
    for (int i = lane; i < HID; i += 32)
        sum += h[(size_t)t * HID + i] * rw[i * NEXP + e];
#pragma unroll
    for (int o = 16; o > 0; o >>= 1) sum += __shfl_down_sync(0xffffffffu, sum, o);
    __shared__ float logits[NEXP];
    if (lane == 0) logits[e] = sum + rb[e];
    __syncthreads();
    if (tid == 0) {
        float mx = logits[0];
        for (int i = 1; i < NEXP; i++) mx = fmaxf(mx, logits[i]);
        float ex[NEXP], ssum = 0.f;
        for (int i = 0; i < NEXP; i++) { ex[i] = expf(logits[i] - mx); ssum += ex[i]; }
        float p[NEXP];
        for (int i = 0; i < NEXP; i++) p[i] = ex[i] / ssum;
        int i0 = 0;
        for (int i = 1; i < NEXP; i++) if (p[i] > p[i0]) i0 = i;
        int i1 = (i0 == 0) ? 1 : 0;
        for (int i = 0; i < NEXP; i++) if (i != i0 && p[i] > p[i1]) i1 = i;
        float b = expf(p[i1] - p[i0]);
        float g0 = 1.f / (1.f + b);
        float g1 = b / (1.f + b);
        gates[t * 2] = g0; gates[t * 2 + 1] = g1;
        texp[t * 2] = i0; texp[t * 2 + 1] = i1;
        tlocal[t * 2]     = atomicAdd(&cnt[i0], 1);
        tlocal[t * 2 + 1] = atomicAdd(&cnt[i1], 1);
    }
}

__global__ __launch_bounds__(256) void assign_kernel(
    const int* __restrict__ cnt, int* __restrict__ offs, int* __restrict__ perm,
    const int* __restrict__ texp, const int* __restrict__ tlocal,
    int* __restrict__ tslot, int* __restrict__ loads)
{
    __shared__ int so[NEXP];
    if (threadIdx.x == 0) {
        int acc = 0;
        for (int e = 0; e < NEXP; e++) {
            so[e] = acc; offs[e] = acc; loads[e] = cnt[e]; acc += cnt[e];
        }
    }
    __syncthreads();
    for (int i = threadIdx.x; i < 2 * SQ; i += blockDim.x) {
        int t = i >> 1;
        int slot = so[texp[i]] + tlocal[i];
        perm[slot] = t;
        tslot[i] = slot;
    }
}

__global__ void loss_kernel(const int* __restrict__ loads, float* __restrict__ out) {
    int l = threadIdx.x;
    if (l < NLAY) {
        float mean = (float)(2 * SQ) / (float)NEXP;
        float var = 0.f;
        for (int e = 0; e < NEXP; e++) {
            float d = (float)loads[l * NEXP + e] - mean;
            var += d * d;
        }
        var /= (float)(NEXP - 1);
        out[l] = var / (mean * mean);
    }
}

// ---------------- host launch ----------------
extern "C" void kernel_launch(void* const* d_in, const int* in_sizes, int n_in,
                              void* d_out, int out_size) {
    const int*   ids   = (const int*)d_in[0];
    const int*   amask = (const int*)d_in[1];
    const float* emb   = (const float*)d_in[2];
    const float* pos   = (const float*)d_in[3];
    const float* qw    = (const float*)d_in[4];
    const float* qb    = (const float*)d_in[5];
    const float* kw    = (const float*)d_in[6];
    const float* kb    = (const float*)d_in[7];
    const float* vw    = (const float*)d_in[8];
    const float* vb    = (const float*)d_in[9];
    const float* rw    = (const float*)d_in[10];
    const float* rb    = (const float*)d_in[11];
    const float* fc1w  = (const float*)d_in[12];
    const float* fc1b  = (const float*)d_in[13];
    const float* fc2w  = (const float*)d_in[14];
    const float* fc2b  = (const float*)d_in[15];
    const float* lng   = (const float*)d_in[16];
    const float* lnb   = (const float*)d_in[17];
    const float* ow    = (const float*)d_in[18];
    const float* ob    = (const float*)d_in[19];
    float* out = (float*)d_out;

    cudaFuncSetAttribute(mma_gemm<false, false, false, true>,
                         cudaFuncAttributeMaxDynamicSharedMemorySize, GEMM_SMEM);
    cudaFuncSetAttribute(mma_gemm<true, true, true, false>,
                         cudaFuncAttributeMaxDynamicSharedMemorySize, GEMM_SMEM);
    cudaFuncSetAttribute(mma_gemm<false, true, false, false>,
                         cudaFuncAttributeMaxDynamicSharedMemorySize, GEMM_SMEM);
    cudaFuncSetAttribute(mma_gemm_bf16,
                         cudaFuncAttributeMaxDynamicSharedMemorySize, GEMM_SMEM_BF);

    float *h, *res, *qkv, *part, *wqkv, *bqkv, *h1, *eo, *gates;
    int *texp, *tlocal, *tslot, *cnt, *offs, *perm, *loads;
    cudaGetSymbolAddress((void**)&h, g_h);
    cudaGetSymbolAddress((void**)&res, g_res);
    cudaGetSymbolAddress((void**)&qkv, g_qkv);
    cudaGetSymbolAddress((void**)&part, g_part);
    cudaGetSymbolAddress((void**)&wqkv, g_wqkv);
    cudaGetSymbolAddress((void**)&bqkv, g_bqkv);
    cudaGetSymbolAddress((void**)&h1, g_h1);
    cudaGetSymbolAddress((void**)&eo, g_eo);
    cudaGetSymbolAddress((void**)&gates, g_gates);
    cudaGetSymbolAddress((void**)&texp, g_texp);
    cudaGetSymbolAddress((void**)&tlocal, g_tlocal);
    cudaGetSymbolAddress((void**)&tslot, g_tslot);
    cudaGetSymbolAddress((void**)&cnt, g_cnt);
    cudaGetSymbolAddress((void**)&offs, g_offs);
    cudaGetSymbolAddress((void**)&perm, g_perm);
    cudaGetSymbolAddress((void**)&loads, g_loads);

    {
        size_t tot = (size_t)NLAY * HID * QKVN;
        pack_qkv_w<<<(unsigned)((tot + 255) / 256), 256>>>(qw, kw, vw, wqkv);
        pack_qkv_b<<<(NLAY * QKVN + 255) / 256, 256>>>(qb, kb, vb, bqkv);
    }

    embed_kernel<<<SQ, 256>>>(ids, emb, pos, h);

    for (int l = 0; l < NLAY; l++) {
        const float* rw_l = rw + (size_t)l * HID * NEXP;
        const float* rb_l = rb + (size_t)l * NEXP;
        const float* fc1w_l = fc1w + (size_t)l * NEXP * HID * FFD;
        const float* fc1b_l = fc1b + (size_t)l * NEXP * FFD;
        const float* fc2w_l = fc2w + (size_t)l * NEXP * FFD * HID;
        const float* fc2b_l = fc2b + (size_t)l * NEXP * HID;

        // fused QKV projection with split-K x2: [1024,768] @ [768,1280]
        {
            dim3 grid(QKVN / 128, SQ / 64, 2);
            mma_gemm<false, false, false, true><<<grid, 256, GEMM_SMEM>>>(
                h, wqkv + (size_t)l * HID * QKVN, nullptr,
                part, SQ, QKVN, HID, HID, QKVN, nullptr, nullptr, nullptr, 0, 0);
            add_qkv_kernel<<<SQ * QKVN / 256, 256>>>(
                part, bqkv + (size_t)l * QKVN, qkv);
        }

        attn_kernel<<<dim3(SQ / 64, NHD), 256>>>(qkv, amask, res);
        ln_kernel<<<SQ, 256>>>(h, res, lng, lnb, cnt);

        router_kernel<<<SQ, 256>>>(h, rw_l, rb_l, gates, texp, tlocal, cnt);
        assign_kernel<<<1, 256>>>(cnt, offs, perm, texp, tlocal, tslot, loads + l * NEXP);

        {   // fc1 + gelu (gathered rows)
            dim3 grid(FFD / 128, SQ / 64, NEXP);
            mma_gemm<true, true, true, false><<<grid, 256, GEMM_SMEM>>>(
                h, fc1w_l, fc1b_l, h1, SQ, FFD, HID, HID, FFD,
                perm, offs, cnt, (size_t)HID * FFD, (size_t)FFD);
        }
        {   // fc2 (contiguous slots)
            dim3 grid(HID / 128, SQ / 64, NEXP);
            mma_gemm<false, true, false, false><<<grid, 256, GEMM_SMEM>>>(
                h1, fc2w_l, fc2b_l, eo, SQ, HID, FFD, FFD, HID,
                nullptr, offs, cnt, (size_t)FFD * HID, (size_t)HID);
        }
        combine_ln_kernel<<<SQ, 256>>>(h, eo, gates, tslot, lng, lnb);
    }

    // final logits projection: 2xBF16, 128-thread blocks, warp tile 32x64
    {
        dim3 grid(SQ / 64, (NVOC + 127) / 128);
        mma_gemm_bf16<<<grid, 128, GEMM_SMEM_BF>>>(
            h, ow, ob, out, SQ, NVOC, HID, HID, NVOC);
    }
    loss_kernel<<<1, 32>>>(loads, out + ((size_t)out_size - NLAY));
}

// round 17
// speedup vs baseline: 1.2777x; 1.0682x over previous
#include <cuda_runtime.h>
#include <math.h>
#include <stdint.h>

#define SQ   1024
#define HID  768
#define NHD  12
#define DH   64
#define NG   4
#define NLAY 4
#define NEXP 8
#define FFD  3072
#define NVOC 50257
#define QKVN 1280   // 768 + 256 + 256
#define EOFF ((size_t)2 * SQ * HID)   // eo split-K partial offset

// ---------------- scratch (device globals; no allocation) ----------------
__device__ float g_h[SQ * HID];
__device__ float g_res[SQ * HID];
__device__ float g_qkv[SQ * QKVN];
__device__ float g_part[2 * SQ * QKVN];
__device__ float g_wqkv[NLAY * HID * QKVN];
__device__ float g_bqkv[NLAY * QKVN];
__device__ float g_h1[2 * SQ * FFD];
__device__ float g_eo[4 * SQ * HID];    // 2 slots-sets x 2 k-splits
__device__ float g_gates[SQ * 2];
__device__ int   g_texp[SQ * 2];
__device__ int   g_tlocal[SQ * 2];
__device__ int   g_tslot[SQ * 2];
__device__ int   g_cnt[NEXP];
__device__ int   g_offs[NEXP];
__device__ int   g_perm[2 * SQ];
__device__ int   g_loads[NLAY * NEXP];

// ---------------- embedding ----------------
__global__ void embed_kernel(const int* __restrict__ ids,
                             const float* __restrict__ emb,
                             const float* __restrict__ pos,
                             float* __restrict__ h) {
    int s = blockIdx.x;
    int id = ids[s];
    for (int c = threadIdx.x; c < HID; c += blockDim.x)
        h[(size_t)s * HID + c] = emb[(size_t)id * HID + c] + pos[(size_t)s * HID + c];
}

// ---------------- pack qw|kw|vw -> wqkv ----------------
__global__ __launch_bounds__(256) void pack_qkv_w(
    const float* __restrict__ qw, const float* __restrict__ kw,
    const float* __restrict__ vw, float* __restrict__ wqkv)
{
    size_t idx = (size_t)blockIdx.x * 256 + threadIdx.x;
    if (idx >= (size_t)NLAY * HID * QKVN) return;
    int j = (int)(idx % QKVN);
    size_t li = idx / QKVN;
    float v;
    if (j < HID)            v = qw[li * HID + j];
    else if (j < HID + 256) v = kw[li * 256 + (j - HID)];
    else                    v = vw[li * 256 + (j - HID - 256)];
    wqkv[idx] = v;
}

__global__ void pack_qkv_b(const float* __restrict__ qb, const float* __restrict__ kb,
                           const float* __restrict__ vb, float* __restrict__ bqkv)
{
    int idx = blockIdx.x * 256 + threadIdx.x;
    if (idx >= NLAY * QKVN) return;
    int l = idx / QKVN, j = idx % QKVN;
    float v;
    if (j < HID)            v = qb[l * HID + j];
    else if (j < HID + 256) v = kb[l * 256 + (j - HID)];
    else                    v = vb[l * 256 + (j - HID - 256)];
    bqkv[idx] = v;
}

// qkv = part0 + part1 + bias
__global__ __launch_bounds__(256) void add_qkv_kernel(
    const float* __restrict__ part, const float* __restrict__ bias,
    float* __restrict__ qkv)
{
    int i = blockIdx.x * 256 + threadIdx.x;
    qkv[i] = part[i] + part[SQ * QKVN + i] + bias[i % QKVN];
}

// ---------------- tf32 helpers ----------------
__device__ __forceinline__ uint32_t f2tf(float x) {
    uint32_t r;
    asm("cvt.rna.tf32.f32 %0, %1;" : "=r"(r) : "f"(x));
    return r;
}

__device__ __forceinline__ void mma_tf32(float c[4],
                                         uint32_t a0, uint32_t a1, uint32_t a2, uint32_t a3,
                                         uint32_t b0, uint32_t b1) {
    asm volatile(
        "mma.sync.aligned.m16n8k8.row.col.f32.tf32.tf32.f32 "
        "{%0,%1,%2,%3}, {%4,%5,%6,%7}, {%8,%9}, {%0,%1,%2,%3};"
        : "+f"(c[0]), "+f"(c[1]), "+f"(c[2]), "+f"(c[3])
        : "r"(a0), "r"(a1), "r"(a2), "r"(a3), "r"(b0), "r"(b1));
}

__device__ __forceinline__ uint4 tf_pack(float v0, float v4) {
    uint4 p;
    p.x = f2tf(v0);
    p.y = f2tf(v4);
    p.z = f2tf(v0 - __uint_as_float(p.x));
    p.w = f2tf(v4 - __uint_as_float(p.y));
    return p;
}

// ---------------- bf16 helpers ----------------
__device__ __forceinline__ uint32_t bf16pack2(float x0, float x1) {
    uint32_t r;
    asm("cvt.rn.bf16x2.f32 %0, %1, %2;" : "=r"(r) : "f"(x1), "f"(x0));
    return r;
}
__device__ __forceinline__ void bf16split2(float x0, float x1, uint32_t& hi, uint32_t& lo) {
    hi = bf16pack2(x0, x1);
    float h0 = __uint_as_float(hi << 16);
    float h1 = __uint_as_float(hi & 0xFFFF0000u);
    lo = bf16pack2(x0 - h0, x1 - h1);
}

__device__ __forceinline__ void mma_bf16(float c[4],
                                         uint32_t a0, uint32_t a1, uint32_t a2, uint32_t a3,
                                         uint32_t b0, uint32_t b1) {
    asm volatile(
        "mma.sync.aligned.m16n8k16.row.col.f32.bf16.bf16.f32 "
        "{%0,%1,%2,%3}, {%4,%5,%6,%7}, {%8,%9}, {%0,%1,%2,%3};"
        : "+f"(c[0]), "+f"(c[1]), "+f"(c[2]), "+f"(c[3])
        : "r"(a0), "r"(a1), "r"(a2), "r"(a3), "r"(b0), "r"(b1));
}

#define ASTG 576            // 64 rows * 9 uint4
#define BSTG 1152           // 128 rows * 9 uint4
#define GEMM_SMEM (2 * (ASTG + BSTG) * 16)   // 55296 bytes

// ---------------- 3xTF32 GEMM: 64(M)x128(N) tile, double-buffered ----------
// SPLITK && !EXPERT: blockIdx.z in {0,1} takes K/2; raw partial -> C + z*M*ldc
// SPLITK && EXPERT:  blockIdx.z = e*2 + kz; raw partial -> C + kz*EOFF
template<bool GELU, bool EXPERT, bool GATHER, bool SPLITK>
__global__ __launch_bounds__(256, 2) void mma_gemm(
    const float* __restrict__ A, const float* __restrict__ B,
    const float* __restrict__ bias, float* __restrict__ C,
    int M, int N, int K, int lda, int ldc,
    const int* __restrict__ perm, const int* __restrict__ offs,
    const int* __restrict__ cnts, size_t strideB, size_t strideBias)
{
    extern __shared__ uint4 sm4[];
    uint4* AP = sm4;
    uint4* BP = sm4 + 2 * ASTG;

    int mcount = M, base = 0;
    if (EXPERT) {
        int z = blockIdx.z;
        int e = SPLITK ? (z >> 1) : z;
        mcount = cnts[e];
        base   = offs[e];
        B     += (size_t)e * strideB;
        bias  += (size_t)e * strideBias;
        if (SPLITK) {
            int kz = z & 1;
            int kb = (K >> 1) * kz;
            A += kb;
            B += (size_t)kb * (size_t)N;
            C += (size_t)kz * EOFF;
            K >>= 1;
        }
    } else if (SPLITK) {
        int z = blockIdx.z;
        int kb = (K >> 1) * z;
        A += kb;
        B += (size_t)kb * (size_t)N;
        C += (size_t)z * (size_t)M * (size_t)ldc;
        K >>= 1;
    }
    int m0 = blockIdx.y * 64;
    if (m0 >= mcount) return;
    int n0 = blockIdx.x * 128;

    int tid = threadIdx.x, lane = tid & 31, warp = tid >> 5;
    int wm = (warp & 1) * 32;
    int wn = (warp >> 1) * 32;

    int aRow = tid >> 1;
    int aKK  = tid & 1;
    bool aprod = (tid < 128);
    bool aok = aprod && (m0 + aRow < mcount);
    const float* aptr = A;
    if (aok) {
        int phys = GATHER ? perm[base + m0 + aRow]
                          : (EXPERT ? base + m0 + aRow : m0 + aRow);
        aptr = A + (size_t)phys * (size_t)lda;
    }
    int bN   = tid & 127;
    int bKQ0 = tid >> 7;
    int gn   = n0 + bN;
    bool bok = (gn < N);

    float c[2][4][4];
#pragma unroll
    for (int i = 0; i < 2; i++)
#pragma unroll
        for (int j = 0; j < 4; j++)
#pragma unroll
            for (int q = 0; q < 4; q++) c[i][j][q] = 0.f;

    float stA[8], stB[8];

    if (aprod) {
        float4 v0 = make_float4(0.f,0.f,0.f,0.f), v1 = v0;
        if (aok) {
            v0 = *(const float4*)(aptr + aKK * 8);
            v1 = *(const float4*)(aptr + aKK * 8 + 4);
        }
        stA[0]=v0.x; stA[1]=v0.y; stA[2]=v0.z; stA[3]=v0.w;
        stA[4]=v1.x; stA[5]=v1.y; stA[6]=v1.z; stA[7]=v1.w;
    }
#pragma unroll
    for (int j = 0; j < 4; j++) {
        int kq = bKQ0 + 2 * j;
        int krow = (kq >> 2) * 8 + (kq & 3);
        float b0 = 0.f, b1 = 0.f;
        if (bok) {
            b0 = B[(size_t)krow * (size_t)N + gn];
            b1 = B[(size_t)(krow + 4) * (size_t)N + gn];
        }
        stB[j * 2] = b0; stB[j * 2 + 1] = b1;
    }
    if (aprod) {
#pragma unroll
        for (int q = 0; q < 4; q++)
            AP[aRow * 9 + aKK * 4 + q] = tf_pack(stA[q], stA[q + 4]);
    }
#pragma unroll
    for (int j = 0; j < 4; j++) {
        int kq = bKQ0 + 2 * j;
        BP[bN * 9 + kq] = tf_pack(stB[j * 2], stB[j * 2 + 1]);
    }
    __syncthreads();

    int buf = 0;
    for (int k0 = 0; k0 < K; k0 += 16) {
        bool has_next = (k0 + 16 < K);
        if (has_next) {
            if (aprod) {
                float4 v0 = make_float4(0.f,0.f,0.f,0.f), v1 = v0;
                if (aok) {
                    v0 = *(const float4*)(aptr + k0 + 16 + aKK * 8);
                    v1 = *(const float4*)(aptr + k0 + 16 + aKK * 8 + 4);
                }
                stA[0]=v0.x; stA[1]=v0.y; stA[2]=v0.z; stA[3]=v0.w;
                stA[4]=v1.x; stA[5]=v1.y; stA[6]=v1.z; stA[7]=v1.w;
            }
#pragma unroll
            for (int j = 0; j < 4; j++) {
                int kq = bKQ0 + 2 * j;
                int krow = k0 + 16 + (kq >> 2) * 8 + (kq & 3);
                float b0 = 0.f, b1 = 0.f;
                if (bok) {
                    b0 = B[(size_t)krow * (size_t)N + gn];
                    b1 = B[(size_t)(krow + 4) * (size_t)N + gn];
                }
                stB[j * 2] = b0; stB[j * 2 + 1] = b1;
            }
        }

        const uint4* APc = AP + buf * ASTG;
        const uint4* BPc = BP + buf * BSTG;
        int ra = lane >> 2;
        int q  = lane & 3;
#pragma unroll
        for (int kk = 0; kk < 2; kk++) {
            int kkq = kk * 4 + q;
            uint32_t aH[2][4], aL[2][4];
#pragma unroll
            for (int fm = 0; fm < 2; fm++) {
                int m = wm + fm * 16 + ra;
                uint4 f0 = APc[m * 9 + kkq];
                uint4 f1 = APc[(m + 8) * 9 + kkq];
                aH[fm][0] = f0.x; aH[fm][1] = f1.x;
                aH[fm][2] = f0.y; aH[fm][3] = f1.y;
                aL[fm][0] = f0.z; aL[fm][1] = f1.z;
                aL[fm][2] = f0.w; aL[fm][3] = f1.w;
            }
#pragma unroll
            for (int fn = 0; fn < 4; fn++) {
                int n = wn + fn * 8 + ra;
                uint4 fb = BPc[n * 9 + kkq];
#pragma unroll
                for (int fm = 0; fm < 2; fm++) {
                    mma_tf32(c[fm][fn], aL[fm][0], aL[fm][1], aL[fm][2], aL[fm][3], fb.x, fb.y);
                    mma_tf32(c[fm][fn], aH[fm][0], aH[fm][1], aH[fm][2], aH[fm][3], fb.z, fb.w);
                    mma_tf32(c[fm][fn], aH[fm][0], aH[fm][1], aH[fm][2], aH[fm][3], fb.x, fb.y);
                }
            }
        }

        if (has_next) {
            uint4* APn = AP + (buf ^ 1) * ASTG;
            uint4* BPn = BP + (buf ^ 1) * BSTG;
            if (aprod) {
#pragma unroll
                for (int qq = 0; qq < 4; qq++)
                    APn[aRow * 9 + aKK * 4 + qq] = tf_pack(stA[qq], stA[qq + 4]);
            }
#pragma unroll
            for (int j = 0; j < 4; j++) {
                int kq = bKQ0 + 2 * j;
                BPn[bN * 9 + kq] = tf_pack(stB[j * 2], stB[j * 2 + 1]);
            }
        }
        __syncthreads();
        buf ^= 1;
    }

#pragma unroll
    for (int fm = 0; fm < 2; fm++) {
#pragma unroll
        for (int half = 0; half < 2; half++) {
            int mrel = m0 + wm + fm * 16 + (lane >> 2) + half * 8;
            if (mrel >= mcount) continue;
            size_t crow = (size_t)(EXPERT ? base + mrel : mrel) * (size_t)ldc;
#pragma unroll
            for (int fn = 0; fn < 4; fn++) {
                int n = n0 + wn + fn * 8 + (lane & 3) * 2;
                float v0 = c[fm][fn][half * 2 + 0];
                float v1 = c[fm][fn][half * 2 + 1];
                if (n < N) {
                    float o = SPLITK ? v0 : v0 + bias[n];
                    if (GELU) o = 0.5f * o * (1.f + erff(o * 0.70710678118654752f));
                    C[crow + n] = o;
                }
                if (n + 1 < N) {
                    float o = SPLITK ? v1 : v1 + bias[n + 1];
                    if (GELU) o = 0.5f * o * (1.f + erff(o * 0.70710678118654752f));
                    C[crow + n + 1] = o;
                }
            }
        }
    }
}

// ---------------- 2xBF16 GEMM (logits): 128 threads, warp tile 32x64 -------
#define BA_STG (64 * 5)
#define BB_STG (128 * 5)
#define GEMM_SMEM_BF (2 * (BA_STG + BB_STG) * 16)   // 30720 bytes

__global__ __launch_bounds__(128) void mma_gemm_bf16(
    const float* __restrict__ A, const float* __restrict__ B,
    const float* __restrict__ bias, float* __restrict__ C,
    int M, int N, int K, int lda, int ldc)
{
    extern __shared__ uint4 sm4[];
    uint4* AP = sm4;
    uint4* BP = sm4 + 2 * BA_STG;

    int m0 = blockIdx.x * 64;
    int n0 = blockIdx.y * 128;

    int tid = threadIdx.x, lane = tid & 31, warp = tid >> 5;
    int wm = (warp & 1) * 32;
    int wn = (warp >> 1) * 64;

    int aRow = tid >> 1;
    int aH2  = tid & 1;
    bool aok = (m0 + aRow < M);
    const float* aptr = A + (size_t)(m0 + aRow) * (size_t)lda;

    int bN = tid;
    int gn = n0 + bN;
    bool bok = (gn < N);

    float c[2][8][4];
#pragma unroll
    for (int i = 0; i < 2; i++)
#pragma unroll
        for (int j = 0; j < 8; j++)
#pragma unroll
            for (int q = 0; q < 4; q++) c[i][j][q] = 0.f;

    float sA[8], sB[16];

    {
        float4 v0 = make_float4(0.f,0.f,0.f,0.f), v1 = v0;
        if (aok) {
            v0 = *(const float4*)(aptr + aH2 * 4);
            v1 = *(const float4*)(aptr + aH2 * 4 + 8);
        }
        sA[0]=v0.x; sA[1]=v0.y; sA[2]=v0.z; sA[3]=v0.w;
        sA[4]=v1.x; sA[5]=v1.y; sA[6]=v1.z; sA[7]=v1.w;
    }
#pragma unroll
    for (int q = 0; q < 4; q++) {
        int k = 2 * q;
        float b0=0.f, b1=0.f, b2=0.f, b3=0.f;
        if (bok) {
            b0 = B[(size_t)k * N + gn];
            b1 = B[(size_t)(k + 1) * N + gn];
            b2 = B[(size_t)(k + 8) * N + gn];
            b3 = B[(size_t)(k + 9) * N + gn];
        }
        sB[q*4+0]=b0; sB[q*4+1]=b1; sB[q*4+2]=b2; sB[q*4+3]=b3;
    }
#pragma unroll
    for (int j = 0; j < 2; j++) {
        uint4 p;
        bf16split2(sA[j*2+0], sA[j*2+1], p.x, p.z);
        bf16split2(sA[j*2+4], sA[j*2+5], p.y, p.w);
        AP[aRow * 5 + 2 * aH2 + j] = p;
    }
#pragma unroll
    for (int q = 0; q < 4; q++) {
        uint4 p;
        bf16split2(sB[q*4+0], sB[q*4+1], p.x, p.z);
        bf16split2(sB[q*4+2], sB[q*4+3], p.y, p.w);
        BP[bN * 5 + q] = p;
    }
    __syncthreads();

    int buf = 0;
    for (int k0 = 0; k0 < K; k0 += 16) {
        bool has_next = (k0 + 16 < K);
        if (has_next) {
            float4 v0 = make_float4(0.f,0.f,0.f,0.f), v1 = v0;
            if (aok) {
                v0 = *(const float4*)(aptr + k0 + 16 + aH2 * 4);
                v1 = *(const float4*)(aptr + k0 + 16 + aH2 * 4 + 8);
            }
            sA[0]=v0.x; sA[1]=v0.y; sA[2]=v0.z; sA[3]=v0.w;
            sA[4]=v1.x; sA[5]=v1.y; sA[6]=v1.z; sA[7]=v1.w;
#pragma unroll
            for (int q = 0; q < 4; q++) {
                int k = k0 + 16 + 2 * q;
                float b0=0.f, b1=0.f, b2=0.f, b3=0.f;
                if (bok) {
                    b0 = B[(size_t)k * N + gn];
                    b1 = B[(size_t)(k + 1) * N + gn];
                    b2 = B[(size_t)(k + 8) * N + gn];
                    b3 = B[(size_t)(k + 9) * N + gn];
                }
                sB[q*4+0]=b0; sB[q*4+1]=b1; sB[q*4+2]=b2; sB[q*4+3]=b3;
            }
        }

        const uint4* APc = AP + buf * BA_STG;
        const uint4* BPc = BP + buf * BB_STG;
        int ra = lane >> 2;
        int q  = lane & 3;
        uint32_t aHf[2][4], aLf[2][4];
#pragma unroll
        for (int fm = 0; fm < 2; fm++) {
            int m = wm + fm * 16 + ra;
            uint4 f0 = APc[m * 5 + q];
            uint4 f1 = APc[(m + 8) * 5 + q];
            aHf[fm][0] = f0.x; aHf[fm][1] = f1.x;
            aHf[fm][2] = f0.y; aHf[fm][3] = f1.y;
            aLf[fm][0] = f0.z; aLf[fm][1] = f1.z;
            aLf[fm][2] = f0.w; aLf[fm][3] = f1.w;
        }
#pragma unroll
        for (int fn = 0; fn < 8; fn++) {
            uint4 fb = BPc[(wn + fn * 8 + ra) * 5 + q];
#pragma unroll
            for (int fm = 0; fm < 2; fm++) {
                mma_bf16(c[fm][fn], aLf[fm][0], aLf[fm][1], aLf[fm][2], aLf[fm][3], fb.x, fb.y);
                mma_bf16(c[fm][fn], aHf[fm][0], aHf[fm][1], aHf[fm][2], aHf[fm][3], fb.z, fb.w);
                mma_bf16(c[fm][fn], aHf[fm][0], aHf[fm][1], aHf[fm][2], aHf[fm][3], fb.x, fb.y);
            }
        }

        if (has_next) {
            uint4* APn = AP + (buf ^ 1) * BA_STG;
            uint4* BPn = BP + (buf ^ 1) * BB_STG;
#pragma unroll
            for (int j = 0; j < 2; j++) {
                uint4 p;
                bf16split2(sA[j*2+0], sA[j*2+1], p.x, p.z);
                bf16split2(sA[j*2+4], sA[j*2+5], p.y, p.w);
                APn[aRow * 5 + 2 * aH2 + j] = p;
            }
#pragma unroll
            for (int q2 = 0; q2 < 4; q2++) {
                uint4 p;
                bf16split2(sB[q2*4+0], sB[q2*4+1], p.x, p.z);
                bf16split2(sB[q2*4+2], sB[q2*4+3], p.y, p.w);
                BPn[bN * 5 + q2] = p;
            }
        }
        __syncthreads();
        buf ^= 1;
    }

#pragma unroll
    for (int fm = 0; fm < 2; fm++) {
#pragma unroll
        for (int half = 0; half < 2; half++) {
            int mrel = m0 + wm + fm * 16 + (lane >> 2) + half * 8;
            if (mrel >= M) continue;
            size_t crow = (size_t)mrel * (size_t)ldc;
#pragma unroll
            for (int fn = 0; fn < 8; fn++) {
                int n = n0 + wn + fn * 8 + (lane & 3) * 2;
                if (n < N)     C[crow + n]     = c[fm][fn][half * 2 + 0] + bias[n];
                if (n + 1 < N) C[crow + n + 1] = c[fm][fn][half * 2 + 1] + bias[n + 1];
            }
        }
    }
}

// ---------------- flash-style GQA attention (fp32, reads combined QKV) ----------------
__global__ __launch_bounds__(256) void attn_kernel(
    const float* __restrict__ qkv, const int* __restrict__ amask,
    float* __restrict__ ao)
{
    const float SCALE = 0.125f;
    int head = blockIdx.y;
    int g    = head / (NHD / NG);
    int q0   = blockIdx.x * 64;

    __shared__ float QsT[64][68];
    __shared__ float KsT[64][33];
    __shared__ float Vs [32][68];
    __shared__ float PsT[32][68];
    __shared__ float Mk [32];

    int tid = threadIdx.x;
#pragma unroll
    for (int i = 0; i < 4; i++) {
        int idx = tid + i * 256;
        int r = idx >> 4;
        int dseg = (idx & 15) * 4;
        float4 qv = *(const float4*)(qkv + (size_t)(q0 + r) * QKVN + head * 64 + dseg);
        QsT[dseg + 0][r] = qv.x; QsT[dseg + 1][r] = qv.y;
        QsT[dseg + 2][r] = qv.z; QsT[dseg + 3][r] = qv.w;
    }

    int rg = tid >> 4, kg = tid & 15;
    int r0 = rg * 4, d0 = kg * 4, j0 = kg * 2;

    float acc[4][4] = {};
    float m[4], l[4];
#pragma unroll
    for (int i = 0; i < 4; i++) { m[i] = -3.0e38f; l[i] = 0.f; }

    for (int kc = 0; kc < 32; kc++) {
        int kbase = kc * 32;
#pragma unroll
        for (int i = 0; i < 2; i++) {
            int idx = tid + i * 256;
            int kk = idx >> 4;
            int dseg = (idx & 15) * 4;
            float4 kv = *(const float4*)(qkv + (size_t)(kbase + kk) * QKVN + HID + g * 64 + dseg);
            KsT[dseg + 0][kk] = kv.x; KsT[dseg + 1][kk] = kv.y;
            KsT[dseg + 2][kk] = kv.z; KsT[dseg + 3][kk] = kv.w;
            float4 vv = *(const float4*)(qkv + (size_t)(kbase + kk) * QKVN + HID + 256 + g * 64 + dseg);
            *(float4*)&Vs[kk][dseg] = vv;
        }
        if (tid < 32) Mk[tid] = (amask[kbase + tid] == 0) ? -3.0e38f : 0.f;
        __syncthreads();

        float s0[4] = {}, s1[4] = {};
#pragma unroll
        for (int d = 0; d < 64; d++) {
            float4 a = *(const float4*)&QsT[d][r0];
            float b0 = KsT[d][j0], b1 = KsT[d][j0 + 1];
            s0[0] += a.x * b0; s1[0] += a.x * b1;
            s0[1] += a.y * b0; s1[1] += a.y * b1;
            s0[2] += a.z * b0; s1[2] += a.z * b1;
            s0[3] += a.w * b0; s1[3] += a.w * b1;
        }
        float mk0 = Mk[j0], mk1 = Mk[j0 + 1];
        float cm[4];
#pragma unroll
        for (int i = 0; i < 4; i++) {
            s0[i] = s0[i] * SCALE + mk0;
            s1[i] = s1[i] * SCALE + mk1;
            cm[i] = fmaxf(s0[i], s1[i]);
        }
#pragma unroll
        for (int o = 1; o < 16; o <<= 1)
#pragma unroll
            for (int i = 0; i < 4; i++)
                cm[i] = fmaxf(cm[i], __shfl_xor_sync(0xffffffffu, cm[i], o));

        float p0[4], p1[4], csum[4];
#pragma unroll
        for (int i = 0; i < 4; i++) {
            float nm = fmaxf(m[i], cm[i]);
            float alpha = expf(m[i] - nm);
            m[i] = nm;
            p0[i] = expf(s0[i] - nm);
            p1[i] = expf(s1[i] - nm);
            csum[i] = p0[i] + p1[i];
            l[i] *= alpha;
#pragma unroll
            for (int j = 0; j < 4; j++) acc[i][j] *= alpha;
        }
#pragma unroll
        for (int o = 1; o < 16; o <<= 1)
#pragma unroll
            for (int i = 0; i < 4; i++)
                csum[i] += __shfl_xor_sync(0xffffffffu, csum[i], o);
#pragma unroll
        for (int i = 0; i < 4; i++) l[i] += csum[i];

#pragma unroll
        for (int i = 0; i < 4; i++) {
            PsT[j0][r0 + i]     = p0[i];
            PsT[j0 + 1][r0 + i] = p1[i];
        }
        __syncthreads();

#pragma unroll
        for (int key = 0; key < 32; key++) {
            float4 pv = *(const float4*)&PsT[key][r0];
            float4 vv = *(const float4*)&Vs[key][d0];
            acc[0][0] += pv.x * vv.x; acc[0][1] += pv.x * vv.y; acc[0][2] += pv.x * vv.z; acc[0][3] += pv.x * vv.w;
            acc[1][0] += pv.y * vv.x; acc[1][1] += pv.y * vv.y; acc[1][2] += pv.y * vv.z; acc[1][3] += pv.y * vv.w;
            acc[2][0] += pv.z * vv.x; acc[2][1] += pv.z * vv.y; acc[2][2] += pv.z * vv.z; acc[2][3] += pv.z * vv.w;
            acc[3][0] += pv.w * vv.x; acc[3][1] += pv.w * vv.y; acc[3][2] += pv.w * vv.z; acc[3][3] += pv.w * vv.w;
        }
        __syncthreads();
    }

#pragma unroll
    for (int i = 0; i < 4; i++) {
        float inv = 1.f / l[i];
        float4 o;
        o.x = acc[i][0] * inv; o.y = acc[i][1] * inv;
        o.z = acc[i][2] * inv; o.w = acc[i][3] * inv;
        *(float4*)(ao + (size_t)(q0 + r0 + i) * HID + head * 64 + d0) = o;
    }
}

// ---------------- layernorm: h = LN(h + res); optionally zero cnt ---------
__global__ __launch_bounds__(256) void ln_kernel(float* __restrict__ h,
                                                 const float* __restrict__ res,
                                                 const float* __restrict__ gam,
                                                 const float* __restrict__ bet,
                                                 int* __restrict__ czero) {
    int row = blockIdx.x;
    __shared__ float xbuf[HID];
    __shared__ float red[256];
    int tid = threadIdx.x;
    if (czero && row == 0 && tid < NEXP) czero[tid] = 0;
    float lsum = 0.f;
    for (int c = tid; c < HID; c += 256) {
        float v = h[(size_t)row * HID + c] + res[(size_t)row * HID + c];
        xbuf[c] = v;
        lsum += v;
    }
    red[tid] = lsum; __syncthreads();
    for (int s = 128; s > 0; s >>= 1) { if (tid < s) red[tid] += red[tid + s]; __syncthreads(); }
    float mean = red[0] / (float)HID;
    __syncthreads();
    float lvar = 0.f;
    for (int c = tid; c < HID; c += 256) { float d = xbuf[c] - mean; lvar += d * d; }
    red[tid] = lvar; __syncthreads();
    for (int s = 128; s > 0; s >>= 1) { if (tid < s) red[tid] += red[tid + s]; __syncthreads(); }
    float rstd = rsqrtf(red[0] / (float)HID + 1e-5f);
    for (int c = tid; c < HID; c += 256)
        h[(size_t)row * HID + c] = (xbuf[c] - mean) * rstd * gam[c] + bet[c];
}

// ---------------- fused MoE combine (+splitK partials +bias) + LN ---------
__global__ __launch_bounds__(256) void combine_ln_kernel(
    float* __restrict__ h, const float* __restrict__ eo,
    const float* __restrict__ gates, const int* __restrict__ tslot,
    const int* __restrict__ texp, const float* __restrict__ fc2b,
    const float* __restrict__ gam, const float* __restrict__ bet)
{
    int row = blockIdx.x;
    int s0 = tslot[row * 2], s1 = tslot[row * 2 + 1];
    int e0 = texp[row * 2],  e1 = texp[row * 2 + 1];
    float g0 = gates[row * 2], g1 = gates[row * 2 + 1];
    const float* b0 = fc2b + (size_t)e0 * HID;
    const float* b1 = fc2b + (size_t)e1 * HID;
    __shared__ float xbuf[HID];
    __shared__ float red[256];
    int tid = threadIdx.x;
    float lsum = 0.f;
    for (int c = tid; c < HID; c += 256) {
        float p0 = eo[(size_t)s0 * HID + c] + eo[EOFF + (size_t)s0 * HID + c] + b0[c];
        float p1 = eo[(size_t)s1 * HID + c] + eo[EOFF + (size_t)s1 * HID + c] + b1[c];
        float v = h[(size_t)row * HID + c] + (g0 * p0 + g1 * p1);
        xbuf[c] = v;
        lsum += v;
    }
    red[tid] = lsum; __syncthreads();
    for (int s = 128; s > 0; s >>= 1) { if (tid < s) red[tid] += red[tid + s]; __syncthreads(); }
    float mean = red[0] / (float)HID;
    __syncthreads();
    float lvar = 0.f;
    for (int c = tid; c < HID; c += 256) { float d = xbuf[c] - mean; lvar += d * d; }
    red[tid] = lvar; __syncthreads();
    for (int s = 128; s > 0; s >>= 1) { if (tid < s) red[tid] += red[tid + s]; __syncthreads(); }
    float rstd = rsqrtf(red[0] / (float)HID + 1e-5f);
    for (int c = tid; c < HID; c += 256)
        h[(size_t)row * HID + c] = (xbuf[c] - mean) * rstd * gam[c] + bet[c];
}

// ---------------- router: top-2 gating ----------------
__global__ __launch_bounds__(256) void router_kernel(
    const float* __restrict__ h, const float* __restrict__ rw,
    const float* __restrict__ rb, float* __restrict__ gates,
    int* __restrict__ texp, int* __restrict__ tlocal, int* __restrict__ cnt)
{
    int t = blockIdx.x;
    int tid = threadIdx.x;
    int e = tid >> 5, lane = tid & 31;
    float sum = 0.f;
    for (int i = lane; i < HID; i += 32)
        sum += h[(size_t)t * HID + i] * rw[i * NEXP + e];
#pragma unroll
    for (int o = 16; o > 0; o >>= 1) sum += __shfl_down_sync(0xffffffffu, sum, o);
    __shared__ float logits[NEXP];
    if (lane == 0) logits[e] = sum + rb[e];
    __syncthreads();
    if (tid == 0) {
        float mx = logits[0];
        for (int i = 1; i < NEXP; i++) mx = fmaxf(mx, logits[i]);
        float ex[NEXP], ssum = 0.f;
        for (int i = 0; i < NEXP; i++) { ex[i] = expf(logits[i] - mx); ssum += ex[i]; }
        float p[NEXP];
        for (int i = 0; i < NEXP; i++) p[i] = ex[i] / ssum;
        int i0 = 0;
        for (int i = 1; i < NEXP; i++) if (p[i] > p[i0]) i0 = i;
        int i1 = (i0 == 0) ? 1 : 0;
        for (int i = 0; i < NEXP; i++) if (i != i0 && p[i] > p[i1]) i1 = i;
        float b = expf(p[i1] - p[i0]);
        float g0 = 1.f / (1.f + b);
        float g1 = b / (1.f + b);
        gates[t * 2] = g0; gates[t * 2 + 1] = g1;
        texp[t * 2] = i0; texp[t * 2 + 1] = i1;
        tlocal[t * 2]     = atomicAdd(&cnt[i0], 1);
        tlocal[t * 2 + 1] = atomicAdd(&cnt[i1], 1);
    }
}

__global__ __launch_bounds__(256) void assign_kernel(
    const int* __restrict__ cnt, int* __restrict__ offs, int* __restrict__ perm,
    const int* __restrict__ texp, const int* __restrict__ tlocal,
    int* __restrict__ tslot, int* __restrict__ loads)
{
    __shared__ int so[NEXP];
    if (threadIdx.x == 0) {
        int acc = 0;
        for (int e = 0; e < NEXP; e++) {
            so[e] = acc; offs[e] = acc; loads[e] = cnt[e]; acc += cnt[e];
        }
    }
    __syncthreads();
    for (int i = threadIdx.x; i < 2 * SQ; i += blockDim.x) {
        int t = i >> 1;
        int slot = so[texp[i]] + tlocal[i];
        perm[slot] = t;
        tslot[i] = slot;
    }
}

__global__ void loss_kernel(const int* __restrict__ loads, float* __restrict__ out) {
    int l = threadIdx.x;
    if (l < NLAY) {
        float mean = (float)(2 * SQ) / (float)NEXP;
        float var = 0.f;
        for (int e = 0; e < NEXP; e++) {
            float d = (float)loads[l * NEXP + e] - mean;
            var += d * d;
        }
        var /= (float)(NEXP - 1);
        out[l] = var / (mean * mean);
    }
}

// ---------------- host launch ----------------
extern "C" void kernel_launch(void* const* d_in, const int* in_sizes, int n_in,
                              void* d_out, int out_size) {
    const int*   ids   = (const int*)d_in[0];
    const int*   amask = (const int*)d_in[1];
    const float* emb   = (const float*)d_in[2];
    const float* pos   = (const float*)d_in[3];
    const float* qw    = (const float*)d_in[4];
    const float* qb    = (const float*)d_in[5];
    const float* kw    = (const float*)d_in[6];
    const float* kb    = (const float*)d_in[7];
    const float* vw    = (const float*)d_in[8];
    const float* vb    = (const float*)d_in[9];
    const float* rw    = (const float*)d_in[10];
    const float* rb    = (const float*)d_in[11];
    const float* fc1w  = (const float*)d_in[12];
    const float* fc1b  = (const float*)d_in[13];
    const float* fc2w  = (const float*)d_in[14];
    const float* fc2b  = (const float*)d_in[15];
    const float* lng   = (const float*)d_in[16];
    const float* lnb   = (const float*)d_in[17];
    const float* ow    = (const float*)d_in[18];
    const float* ob    = (const float*)d_in[19];
    float* out = (float*)d_out;

    cudaFuncSetAttribute(mma_gemm<false, false, false, true>,
                         cudaFuncAttributeMaxDynamicSharedMemorySize, GEMM_SMEM);
    cudaFuncSetAttribute(mma_gemm<true, true, true, false>,
                         cudaFuncAttributeMaxDynamicSharedMemorySize, GEMM_SMEM);
    cudaFuncSetAttribute(mma_gemm<false, true, false, true>,
                         cudaFuncAttributeMaxDynamicSharedMemorySize, GEMM_SMEM);
    cudaFuncSetAttribute(mma_gemm_bf16,
                         cudaFuncAttributeMaxDynamicSharedMemorySize, GEMM_SMEM_BF);

    float *h, *res, *qkv, *part, *wqkv, *bqkv, *h1, *eo, *gates;
    int *texp, *tlocal, *tslot, *cnt, *offs, *perm, *loads;
    cudaGetSymbolAddress((void**)&h, g_h);
    cudaGetSymbolAddress((void**)&res, g_res);
    cudaGetSymbolAddress((void**)&qkv, g_qkv);
    cudaGetSymbolAddress((void**)&part, g_part);
    cudaGetSymbolAddress((void**)&wqkv, g_wqkv);
    cudaGetSymbolAddress((void**)&bqkv, g_bqkv);
    cudaGetSymbolAddress((void**)&h1, g_h1);
    cudaGetSymbolAddress((void**)&eo, g_eo);
    cudaGetSymbolAddress((void**)&gates, g_gates);
    cudaGetSymbolAddress((void**)&texp, g_texp);
    cudaGetSymbolAddress((void**)&tlocal, g_tlocal);
    cudaGetSymbolAddress((void**)&tslot, g_tslot);
    cudaGetSymbolAddress((void**)&cnt, g_cnt);
    cudaGetSymbolAddress((void**)&offs, g_offs);
    cudaGetSymbolAddress((void**)&perm, g_perm);
    cudaGetSymbolAddress((void**)&loads, g_loads);

    {
        size_t tot = (size_t)NLAY * HID * QKVN;
        pack_qkv_w<<<(unsigned)((tot + 255) / 256), 256>>>(qw, kw, vw, wqkv);
        pack_qkv_b<<<(NLAY * QKVN + 255) / 256, 256>>>(qb, kb, vb, bqkv);
    }

    embed_kernel<<<SQ, 256>>>(ids, emb, pos, h);

    for (int l = 0; l < NLAY; l++) {
        const float* rw_l = rw + (size_t)l * HID * NEXP;
        const float* rb_l = rb + (size_t)l * NEXP;
        const float* fc1w_l = fc1w + (size_t)l * NEXP * HID * FFD;
        const float* fc1b_l = fc1b + (size_t)l * NEXP * FFD;
        const float* fc2w_l = fc2w + (size_t)l * NEXP * FFD * HID;
        const float* fc2b_l = fc2b + (size_t)l * NEXP * HID;

        // fused QKV projection with split-K x2
        {
            dim3 grid(QKVN / 128, SQ / 64, 2);
            mma_gemm<false, false, false, true><<<grid, 256, GEMM_SMEM>>>(
                h, wqkv + (size_t)l * HID * QKVN, nullptr,
                part, SQ, QKVN, HID, HID, QKVN, nullptr, nullptr, nullptr, 0, 0);
            add_qkv_kernel<<<SQ * QKVN / 256, 256>>>(
                part, bqkv + (size_t)l * QKVN, qkv);
        }

        attn_kernel<<<dim3(SQ / 64, NHD), 256>>>(qkv, amask, res);
        ln_kernel<<<SQ, 256>>>(h, res, lng, lnb, cnt);

        router_kernel<<<SQ, 256>>>(h, rw_l, rb_l, gates, texp, tlocal, cnt);
        assign_kernel<<<1, 256>>>(cnt, offs, perm, texp, tlocal, tslot, loads + l * NEXP);

        {   // fc1 + gelu (gathered rows)
            dim3 grid(FFD / 128, SQ / 64, NEXP);
            mma_gemm<true, true, true, false><<<grid, 256, GEMM_SMEM>>>(
                h, fc1w_l, fc1b_l, h1, SQ, FFD, HID, HID, FFD,
                perm, offs, cnt, (size_t)HID * FFD, (size_t)FFD);
        }
        {   // fc2 with split-K x2 (raw partials; bias added in combine)
            dim3 grid(HID / 128, SQ / 64, NEXP * 2);
            mma_gemm<false, true, false, true><<<grid, 256, GEMM_SMEM>>>(
                h1, fc2w_l, nullptr, eo, SQ, HID, FFD, FFD, HID,
                nullptr, offs, cnt, (size_t)FFD * HID, 0);
        }
        combine_ln_kernel<<<SQ, 256>>>(h, eo, gates, tslot, texp, fc2b_l, lng, lnb);
    }

    // final logits projection: 2xBF16, 128-thread blocks, warp tile 32x64
    {
        dim3 grid(SQ / 64, (NVOC + 127) / 128);
        mma_gemm_bf16<<<grid, 128, GEMM_SMEM_BF>>>(
            h, ow, ob, out, SQ, NVOC, HID, HID, NVOC);
    }
    loss_kernel<<<1, 32>>>(loads, out + ((size_t)out_size - NLAY));
}